// round 11
// baseline (speedup 1.0000x reference)
#include <cuda_runtime.h>
#include <cuda_fp16.h>
#include <cstdint>
#include <cstddef>

#define NN 512
#define MM 2048
#define FF 1024
#define GG 16
#define DD 64
#define SPLIT 2

// -------- scratch ----------------------------------------------------------
__device__ float  g_Q[NN * FF];                 // Q' = roi@Wq^T + Wq_b + u (fp32)
__device__ __half g_K[MM * FF];                 // K  (fp16, [m][d])
__device__ __half g_VT[FF * MM];                // V^T (fp16, [d][m])
__device__ __half g_L[(size_t)NN * GG * MM];    // w = relu(Wg.emb+b)+1e-6 (fp16)
__device__ float  g_O[SPLIT][NN][FF];           // unnormalized partial outputs
__device__ float  g_Mx[SPLIT][NN][GG];          // partial content-score max
__device__ float  g_Sm[SPLIT][NN][GG];          // partial row sum

__constant__ float c_freq[8] = {
    100.0f,        42.16965034f, 17.78279410f, 7.498942093f,
    3.162277660f,  1.333521432f, 0.5623413252f, 0.2371373706f};

__device__ __forceinline__ uint32_t f2tf32(float f) {
    uint32_t u;
    asm("cvt.rna.tf32.f32 %0, %1;" : "=r"(u) : "f"(f));
    return u;
}

__device__ __forceinline__ uint32_t packh2(float lo, float hi) {
    uint32_t r;
    asm("cvt.rn.f16x2.f32 %0, %1, %2;" : "=r"(r) : "f"(hi), "f"(lo));
    return r;
}

__device__ __forceinline__ void mma_tf32(float* c, const uint32_t* a, const uint32_t* b) {
    asm volatile(
        "mma.sync.aligned.m16n8k8.row.col.f32.tf32.tf32.f32 "
        "{%0,%1,%2,%3}, {%4,%5,%6,%7}, {%8,%9}, {%0,%1,%2,%3};"
        : "+f"(c[0]), "+f"(c[1]), "+f"(c[2]), "+f"(c[3])
        : "r"(a[0]), "r"(a[1]), "r"(a[2]), "r"(a[3]), "r"(b[0]), "r"(b[1]));
}

__device__ __forceinline__ void mma_f16(float* c, const uint32_t* a, const uint32_t* b) {
    asm volatile(
        "mma.sync.aligned.m16n8k16.row.col.f32.f16.f16.f32 "
        "{%0,%1,%2,%3}, {%4,%5,%6,%7}, {%8,%9}, {%0,%1,%2,%3};"
        : "+f"(c[0]), "+f"(c[1]), "+f"(c[2]), "+f"(c[3])
        : "r"(a[0]), "r"(a[1]), "r"(a[2]), "r"(a[3]), "r"(b[0]), "r"(b[1]));
}

__device__ __forceinline__ void cp16(uint32_t d, const void* s) {
    asm volatile("cp.async.cg.shared.global [%0], [%1], 16;" :: "r"(d), "l"(s));
}

// ===========================================================================
// Projection GEMM body (tf32, 128x128 tile, BK=16, double buffered, K=1024).
// mode: 0 = fp32 [i][j]; 1 = fp16 [i][j]; 2 = fp16 T [j][i] (ld MM).
// Called exactly once from the prelude dispatcher (single 32KB smem copy).
// ===========================================================================
__device__ __noinline__ void proj_body(
    const float* __restrict__ A, int lda,
    const float* __restrict__ Bb, int ldb,
    void* __restrict__ Cb, int ldc,
    float alpha,
    const float* __restrict__ cb0, const float* __restrict__ cb1,
    int i0, int j0, int mode)
{
    __shared__ uint32_t sA[2][128 * 16];
    __shared__ uint32_t sB[2][128 * 16];

    const int t = threadIdx.x;
    const int w = t >> 5, lane = t & 31;
    const int g = lane >> 2, tig = lane & 3;
    const int wm = w & 1, wn = w >> 1;

    const float* aPtr[2]; int aIdx[2];
#pragma unroll
    for (int ia = 0; ia < 2; ia++) {
        int fidx = ia * 256 + t;
        int m = fidx >> 2, kq = fidx & 3;
        int ks = kq >> 1, kh = kq & 1;
        int slot = ((m >> 3) & 1) + 2 * kh;
        int tm = m >> 4, gg = m & 7;
        aPtr[ia] = A + (size_t)(i0 + m) * lda + kq * 4;
        aIdx[ia] = ((tm * 2 + ks) * 4 + slot) * 32 + ((gg ^ (slot + 4 * ks)) << 2);
    }
    const float* bPtr[2]; int bIdx[2];
#pragma unroll
    for (int ib = 0; ib < 2; ib++) {
        int fidx = ib * 256 + t;
        int n = fidx >> 2, kq = fidx & 3;
        int ks = kq >> 1, slot = kq & 1;
        int tn = n >> 3, gg = n & 7;
        bPtr[ib] = Bb + (size_t)(j0 + n) * ldb + kq * 4;
        bIdx[ib] = ((tn * 2 + ks) * 2 + slot) * 32 + ((gg ^ (slot * 4 + ks * 2)) << 2);
    }

    float acc[4][4][4];
#pragma unroll
    for (int a = 0; a < 4; a++)
#pragma unroll
        for (int b = 0; b < 4; b++)
#pragma unroll
            for (int c = 0; c < 4; c++) acc[a][b][c] = 0.f;

    const int KT = 64;                      // K = 1024, BK = 16
    float4 ra[2], rb[2];

#pragma unroll
    for (int ia = 0; ia < 2; ia++) { ra[ia] = *(const float4*)(aPtr[ia]);
                                     rb[ia] = *(const float4*)(bPtr[ia]); }
#pragma unroll
    for (int ia = 0; ia < 2; ia++) {
        *(uint4*)&sA[0][aIdx[ia]] = make_uint4(f2tf32(ra[ia].x), f2tf32(ra[ia].y),
                                               f2tf32(ra[ia].z), f2tf32(ra[ia].w));
        *(uint4*)&sB[0][bIdx[ia]] = make_uint4(f2tf32(rb[ia].x), f2tf32(rb[ia].y),
                                               f2tf32(rb[ia].z), f2tf32(rb[ia].w));
    }
    __syncthreads();

#pragma unroll 2
    for (int kt = 0; kt < KT; kt++) {
        const int cur = kt & 1;
        if (kt + 1 < KT) {
#pragma unroll
            for (int ia = 0; ia < 2; ia++) {
                ra[ia] = *(const float4*)(aPtr[ia] + (kt + 1) * 16);
                rb[ia] = *(const float4*)(bPtr[ia] + (kt + 1) * 16);
            }
        }
#pragma unroll
        for (int ks = 0; ks < 2; ks++) {
            uint32_t af[4][4], bf[4][2];
#pragma unroll
            for (int tn = 0; tn < 4; tn++) {
                int tng = wn * 4 + tn;
                int base = ((tng * 2 + ks) * 2) * 32;
                bf[tn][0] = sB[cur][base + ((g ^ (ks * 2)) << 2) + tig];
                bf[tn][1] = sB[cur][base + 32 + ((g ^ (4 + ks * 2)) << 2) + tig];
            }
#pragma unroll
            for (int tm = 0; tm < 4; tm++) {
                int tmg = wm * 4 + tm;
                int base = ((tmg * 2 + ks) * 4) * 32;
#pragma unroll
                for (int s = 0; s < 4; s++)
                    af[tm][s] = sA[cur][base + s * 32 + ((g ^ (s + 4 * ks)) << 2) + tig];
            }
#pragma unroll
            for (int tm = 0; tm < 4; tm++)
#pragma unroll
                for (int tn = 0; tn < 4; tn++)
                    mma_tf32(acc[tm][tn], af[tm], bf[tn]);
        }
        if (kt + 1 < KT) {
            const int nxt = cur ^ 1;
#pragma unroll
            for (int ia = 0; ia < 2; ia++) {
                *(uint4*)&sA[nxt][aIdx[ia]] = make_uint4(f2tf32(ra[ia].x), f2tf32(ra[ia].y),
                                                         f2tf32(ra[ia].z), f2tf32(ra[ia].w));
                *(uint4*)&sB[nxt][bIdx[ia]] = make_uint4(f2tf32(rb[ia].x), f2tf32(rb[ia].y),
                                                         f2tf32(rb[ia].z), f2tf32(rb[ia].w));
            }
        }
        __syncthreads();
    }

#pragma unroll
    for (int tm = 0; tm < 4; tm++) {
        int r = i0 + wm * 64 + tm * 16 + g;
#pragma unroll
        for (int tn = 0; tn < 4; tn++) {
            int c = j0 + wn * 32 + tn * 8 + tig * 2;
            float b0 = 0.f, b1 = 0.f;
            if (cb0) { b0 += cb0[c]; b1 += cb0[c + 1]; }
            if (cb1) { b0 += cb1[c]; b1 += cb1[c + 1]; }
            float v0 = acc[tm][tn][0] * alpha + b0;
            float v1 = acc[tm][tn][1] * alpha + b1;
            float v2 = acc[tm][tn][2] * alpha + b0;
            float v3 = acc[tm][tn][3] * alpha + b1;
            if (mode == 0) {
                float* Cf = (float*)Cb;
                *(float2*)(Cf + (size_t)r * ldc + c) = make_float2(v0, v1);
                *(float2*)(Cf + (size_t)(r + 8) * ldc + c) = make_float2(v2, v3);
            } else if (mode == 1) {
                __half* Ch = (__half*)Cb;
                *(uint32_t*)(Ch + (size_t)r * ldc + c) = packh2(v0, v1);
                *(uint32_t*)(Ch + (size_t)(r + 8) * ldc + c) = packh2(v2, v3);
            } else {
                __half* Ch = (__half*)Cb;        // [j][i], stride MM
                Ch[(size_t)c * MM + r]           = __float2half_rn(v0);
                Ch[(size_t)(c + 1) * MM + r]     = __float2half_rn(v1);
                Ch[(size_t)c * MM + r + 8]       = __float2half_rn(v2);
                Ch[(size_t)(c + 1) * MM + r + 8] = __float2half_rn(v3);
            }
        }
    }
}

// ===========================================================================
// pos body: w[n][g][m] = relu(emb(n,m,:)·Wg[g,:]+b) + 1e-6, fp16 out.
// Block p handles n = p, and n = p + 304 when p < 208 (Wg fragments reused).
// ===========================================================================
__device__ __noinline__ void pos_body(
    int p,
    const float* __restrict__ bbox, const float* __restrict__ ref_bbox,
    const float* __restrict__ Wg_w, const float* __restrict__ Wg_b)
{
    const int t = threadIdx.x;
    const int w = t >> 5, lane = t & 31;
    const int g5 = lane >> 2, t3 = lane & 3;

    uint32_t breg[2][8][2];
#pragma unroll
    for (int tt = 0; tt < 2; tt++)
#pragma unroll
        for (int s = 0; s < 8; s++) {
            breg[tt][s][0] = f2tf32(Wg_w[(8 * tt + g5) * 64 + 8 * s + t3]);
            breg[tt][s][1] = f2tf32(Wg_w[(8 * tt + g5) * 64 + 8 * s + 4 + t3]);
        }
    float bias[2][2];
#pragma unroll
    for (int tt = 0; tt < 2; tt++) {
        bias[tt][0] = Wg_b[8 * tt + 2 * t3];
        bias[tt][1] = Wg_b[8 * tt + 2 * t3 + 1];
    }
    const float fr0 = c_freq[t3], fr1 = c_freq[t3 + 4];

    for (int rep = 0; rep < 2; rep++) {
        if (rep == 1 && p >= 208) break;
        const int n = (rep == 0) ? p : p + 304;

        float x0 = bbox[n * 4 + 0], y0 = bbox[n * 4 + 1];
        float x1 = bbox[n * 4 + 2], y1 = bbox[n * 4 + 3];
        float bw = x1 - x0 + 1.f, bh = y1 - y0 + 1.f;
        float cx = 0.5f * (x0 + x1), cy = 0.5f * (y0 + y1);
        float iw = 1.f / bw, ih = 1.f / bh;
        float lw = __logf(bw), lh = __logf(bh);

        __half* Lpn = g_L + (size_t)n * GG * MM;

        for (int it = 0; it < 16; it++) {
            const int mbase = (it * 8 + w) * 16;
            const int m0p = mbase + g5, m1p = m0p + 8;

            float4 rb0 = *(const float4*)(ref_bbox + (size_t)m0p * 4);
            float4 rb1 = *(const float4*)(ref_bbox + (size_t)m1p * 4);
            float p0[4], p1[4];
            {
                float wr = rb0.z - rb0.x + 1.f, hr = rb0.w - rb0.y + 1.f;
                float cxr = 0.5f * (rb0.x + rb0.z), cyr = 0.5f * (rb0.y + rb0.w);
                p0[0] = __logf(fabsf((cx - cxr) * iw) + 1e-3f);
                p0[1] = __logf(fabsf((cy - cyr) * ih) + 1e-3f);
                p0[2] = lw - __logf(wr);
                p0[3] = lh - __logf(hr);
            }
            {
                float wr = rb1.z - rb1.x + 1.f, hr = rb1.w - rb1.y + 1.f;
                float cxr = 0.5f * (rb1.x + rb1.z), cyr = 0.5f * (rb1.y + rb1.w);
                p1[0] = __logf(fabsf((cx - cxr) * iw) + 1e-3f);
                p1[1] = __logf(fabsf((cy - cyr) * ih) + 1e-3f);
                p1[2] = lw - __logf(wr);
                p1[3] = lh - __logf(hr);
            }

            float ct[2][4];
#pragma unroll
            for (int tt = 0; tt < 2; tt++)
#pragma unroll
                for (int j = 0; j < 4; j++) ct[tt][j] = 0.f;

#pragma unroll
            for (int c = 0; c < 4; c++) {
                float s00, c00, s01, c01, s10, c10, s11, c11;
                __sincosf(p0[c] * fr0, &s00, &c00);
                __sincosf(p0[c] * fr1, &s01, &c01);
                __sincosf(p1[c] * fr0, &s10, &c10);
                __sincosf(p1[c] * fr1, &s11, &c11);
                uint32_t asin_[4] = {f2tf32(s00), f2tf32(s10), f2tf32(s01), f2tf32(s11)};
                uint32_t acos_[4] = {f2tf32(c00), f2tf32(c10), f2tf32(c01), f2tf32(c11)};
                mma_tf32(ct[0], asin_, breg[0][2 * c]);
                mma_tf32(ct[1], asin_, breg[1][2 * c]);
                mma_tf32(ct[0], acos_, breg[0][2 * c + 1]);
                mma_tf32(ct[1], acos_, breg[1][2 * c + 1]);
            }

#pragma unroll
            for (int tt = 0; tt < 2; tt++) {
                int gc = 8 * tt + 2 * t3;
                float v0 = fmaxf(ct[tt][0] + bias[tt][0], 0.f) + 1e-6f;
                float v1 = fmaxf(ct[tt][1] + bias[tt][1], 0.f) + 1e-6f;
                float v2 = fmaxf(ct[tt][2] + bias[tt][0], 0.f) + 1e-6f;
                float v3 = fmaxf(ct[tt][3] + bias[tt][1], 0.f) + 1e-6f;
                Lpn[(size_t)gc * MM + m0p]       = __float2half_rn(v0);
                Lpn[(size_t)(gc + 1) * MM + m0p] = __float2half_rn(v1);
                Lpn[(size_t)gc * MM + m1p]       = __float2half_rn(v2);
                Lpn[(size_t)(gc + 1) * MM + m1p] = __float2half_rn(v3);
            }
        }
    }
}

// ===========================================================================
// Prelude dispatcher: 592 blocks = exactly 2 waves at 2 blocks/SM.
//   even bid with bid/2 < 288 -> proj(bid/2); otherwise pos:
//     odd bid  -> pos id bid/2            (0..295)
//     even bid >= 576 -> pos id 296+(bid-576)/2   (296..303)
// proj id p: p < 32 -> Q projection (grid 8x4); else p-32 -> K|V (grid 16x16).
// ===========================================================================
__global__ void __launch_bounds__(256, 2) prelude_kernel(
    const float* __restrict__ bbox, const float* __restrict__ ref_bbox,
    const float* __restrict__ roi_feat, const float* __restrict__ ref_feat,
    const float* __restrict__ Wg_w, const float* __restrict__ Wg_b,
    const float* __restrict__ Wq_w, const float* __restrict__ Wq_b,
    const float* __restrict__ Wk_w, const float* __restrict__ Wk_b,
    const float* __restrict__ Wv_w, const float* __restrict__ Wv_b,
    const float* __restrict__ u,
    float* __restrict__ Qd, __half* __restrict__ Kd, __half* __restrict__ VTd)
{
    const int bid = blockIdx.x;
    int proj = -1, posn = -1;
    if ((bid & 1) == 0 && (bid >> 1) < 288) {
        proj = bid >> 1;
    } else if (bid & 1) {
        posn = bid >> 1;
    } else {
        posn = 296 + ((bid - 576) >> 1);
    }

    if (posn >= 0) {
        pos_body(posn, bbox, ref_bbox, Wg_w, Wg_b);
        return;
    }

    const float *A, *B, *cb0, *cb1 = nullptr;
    void* C;
    int i0, j0, mode;
    if (proj < 32) {                 // Q projection: grid 8 x 4 over (FF, NN)
        int bx = proj & 7, by = proj >> 3;
        A = roi_feat; B = Wq_w; C = Qd; cb0 = Wq_b; cb1 = u;
        i0 = by * 128; j0 = bx * 128; mode = 0;
    } else {                         // K|V projection: grid 16 x 16 over (2FF, MM)
        int p = proj - 32;
        int bx = p & 15, by = p >> 4;
        A = ref_feat;
        i0 = by * 128; j0 = bx * 128;
        if (j0 < FF) { B = Wk_w; C = Kd; cb0 = Wk_b; mode = 1; }
        else         { B = Wv_w; C = VTd; cb0 = Wv_b; mode = 2; j0 -= FF; }
    }
    proj_body(A, FF, B, FF, C, FF, 1.f, cb0, cb1, i0, j0, mode);
}

// ===========================================================================
// Flash attention (fp16 mma): block = (n-tile 64, head g, split). 2 blocks/SM.
// ===========================================================================
#define KB_U32 (128 * 36)
#define VB_U32 (64 * 68)
#define PP_U32 68
#define FLASH_SMEM_BYTES ((2 * KB_U32 + 2 * VB_U32 + 64 * PP_U32) * 4)
#define FL_TILES ((MM / SPLIT) / 128)   // 8

__global__ void __launch_bounds__(256, 2) flash_kernel()
{
    extern __shared__ uint32_t smem[];
    uint32_t* sK = smem;                           // [2][128][36] u32
    uint32_t* sV = smem + 2 * KB_U32;              // [2][64][68] u32
    uint32_t* sP = smem + 2 * KB_U32 + 2 * VB_U32; // [64][68] u32

    __shared__ float sRmax[2][64];
    __shared__ float sRsum[2][64];

    const int t = threadIdx.x;
    const int w = t >> 5, lane = t & 31;
    const int g5 = lane >> 2, t3 = lane & 3;
    const int wr = w & 3, wc = w >> 2;
    const int n0 = blockIdx.x * 64;
    const int g = blockIdx.y;
    const int sp = blockIdx.z;
    const int m_base = sp * (MM / SPLIT);

    const uint32_t kb = (uint32_t)__cvta_generic_to_shared(sK);
    const uint32_t vb = (uint32_t)__cvta_generic_to_shared(sV);

    // ---- Q tile (64x64 fp32) -> staging -> packed fp16 fragments --------
    {
        float* sPf = (float*)sP;                 // pitch 68 floats
#pragma unroll
        for (int i = 0; i < 4; i++) {
            int f = t + i * 256;
            int row = f >> 4, c4 = (f & 15) << 2;
            *(float4*)&sPf[row * 68 + c4] =
                *(const float4*)(g_Q + (size_t)(n0 + row) * FF + g * 64 + c4);
        }
    }
    __syncthreads();
    const int rl0 = 16 * wr + g5, rl1 = rl0 + 8;
    uint32_t qf[4][4];
    {
        const float* sPf = (const float*)sP;
        int r = 16 * wr + g5;
#pragma unroll
        for (int s = 0; s < 4; s++) {
            float2 x0 = *(const float2*)&sPf[r * 68 + 16 * s + 2 * t3];
            float2 x1 = *(const float2*)&sPf[(r + 8) * 68 + 16 * s + 2 * t3];
            float2 x2 = *(const float2*)&sPf[r * 68 + 16 * s + 2 * t3 + 8];
            float2 x3 = *(const float2*)&sPf[(r + 8) * 68 + 16 * s + 2 * t3 + 8];
            qf[s][0] = packh2(x0.x, x0.y);
            qf[s][1] = packh2(x1.x, x1.y);
            qf[s][2] = packh2(x2.x, x2.y);
            qf[s][3] = packh2(x3.x, x3.y);
        }
    }

    // ---- K / V^T tile loaders (cp.async, fp16) --------------------------
    auto load_kv = [&](int buf, int m0) {
#pragma unroll
        for (int i = 0; i < 4; i++) {            // K: 128 rows x 128B
            int f = t + i * 256;
            int row = f >> 3, h8 = (f & 7) * 8;
            cp16(kb + (uint32_t)((buf * KB_U32 + row * 36) * 4 + h8 * 2),
                 g_K + (size_t)(m0 + row) * FF + g * 64 + h8);
        }
#pragma unroll
        for (int i = 0; i < 4; i++) {            // VT: 64 rows x 256B
            int f = t + i * 256;
            int row = f >> 4, h8 = (f & 15) * 8;
            cp16(vb + (uint32_t)((buf * VB_U32 + row * 68) * 4 + h8 * 2),
                 g_VT + (size_t)(g * 64 + row) * MM + m0 + h8);
        }
        asm volatile("cp.async.commit_group;");
    };

    load_kv(0, m_base);
    __syncthreads();   // Q staging in sP consumed before first P write

    float rmax0 = -1e30f, rmax1 = -1e30f, rsum0 = 0.f, rsum1 = 0.f;
    float oc[4][4];
#pragma unroll
    for (int a = 0; a < 4; a++)
#pragma unroll
        for (int b = 0; b < 4; b++) oc[a][b] = 0.f;

    for (int mt = 0; mt < FL_TILES; mt++) {
        if (mt + 1 < FL_TILES) {
            load_kv((mt + 1) & 1, m_base + (mt + 1) * 128);
            asm volatile("cp.async.wait_group 1;");
        } else {
            asm volatile("cp.async.wait_group 0;");
        }
        __syncthreads();

        const uint32_t* Ku = sK + (mt & 1) * KB_U32;
        const uint32_t* Vu = sV + (mt & 1) * VB_U32;

        // pos weights (fp16, multiplicative)
        __half2 lp0[8], lp1[8];
        {
            size_t base0 = ((size_t)(n0 + rl0) * GG + g) * MM
                         + m_base + mt * 128 + 64 * wc + 2 * t3;
            size_t base1 = base0 + (size_t)8 * GG * MM;
#pragma unroll
            for (int tn = 0; tn < 8; tn++) {
                lp0[tn] = *(const __half2*)(g_L + base0 + 8 * tn);
                lp1[tn] = *(const __half2*)(g_L + base1 + 8 * tn);
            }
        }

        // ---- S = Q K^T ---------------------------------------------------
        float sc[8][4];
#pragma unroll
        for (int a = 0; a < 8; a++)
#pragma unroll
            for (int b = 0; b < 4; b++) sc[a][b] = 0.f;
#pragma unroll
        for (int s = 0; s < 4; s++)
#pragma unroll
            for (int tn = 0; tn < 8; tn++) {
                uint32_t bfr[2];
                int mr = 64 * wc + 8 * tn + g5;
                bfr[0] = Ku[mr * 36 + 8 * s + t3];
                bfr[1] = Ku[mr * 36 + 8 * s + 4 + t3];
                mma_f16(sc[tn], qf[s], bfr);
            }

        // content-score max
        float pm0 = -1e30f, pm1 = -1e30f;
#pragma unroll
        for (int tn = 0; tn < 8; tn++) {
            sc[tn][0] *= 0.125f;
            sc[tn][1] *= 0.125f;
            sc[tn][2] *= 0.125f;
            sc[tn][3] *= 0.125f;
            pm0 = fmaxf(pm0, fmaxf(sc[tn][0], sc[tn][1]));
            pm1 = fmaxf(pm1, fmaxf(sc[tn][2], sc[tn][3]));
        }
        pm0 = fmaxf(pm0, __shfl_xor_sync(~0u, pm0, 1));
        pm0 = fmaxf(pm0, __shfl_xor_sync(~0u, pm0, 2));
        pm1 = fmaxf(pm1, __shfl_xor_sync(~0u, pm1, 1));
        pm1 = fmaxf(pm1, __shfl_xor_sync(~0u, pm1, 2));
        if (t3 == 0) { sRmax[wc][rl0] = pm0; sRmax[wc][rl1] = pm1; }
        __syncthreads();

        float nm0 = fmaxf(rmax0, fmaxf(sRmax[0][rl0], sRmax[1][rl0]));
        float nm1 = fmaxf(rmax1, fmaxf(sRmax[0][rl1], sRmax[1][rl1]));
        float fs0 = __expf(rmax0 - nm0);
        float fs1 = __expf(rmax1 - nm1);
        rmax0 = nm0; rmax1 = nm1;
#pragma unroll
        for (int td = 0; td < 4; td++) {
            oc[td][0] *= fs0; oc[td][1] *= fs0;
            oc[td][2] *= fs1; oc[td][3] *= fs1;
        }

        // ---- P = w * exp(a - max), fp16 into sP -------------------------
        float ps0 = 0.f, ps1 = 0.f;
#pragma unroll
        for (int tn = 0; tn < 8; tn++) {
            float2 w0 = __half22float2(lp0[tn]);
            float2 w1 = __half22float2(lp1[tn]);
            float p0 = w0.x * __expf(sc[tn][0] - nm0);
            float p1 = w0.y * __expf(sc[tn][1] - nm0);
            float p2 = w1.x * __expf(sc[tn][2] - nm1);
            float p3 = w1.y * __expf(sc[tn][3] - nm1);
            ps0 += p0 + p1; ps1 += p2 + p3;
            int colq = 32 * wc + 4 * tn + t3;
            sP[rl0 * PP_U32 + colq] = packh2(p0, p1);
            sP[rl1 * PP_U32 + colq] = packh2(p2, p3);
        }
        ps0 += __shfl_xor_sync(~0u, ps0, 1);
        ps0 += __shfl_xor_sync(~0u, ps0, 2);
        ps1 += __shfl_xor_sync(~0u, ps1, 1);
        ps1 += __shfl_xor_sync(~0u, ps1, 2);
        if (t3 == 0) { sRsum[wc][rl0] = ps0; sRsum[wc][rl1] = ps1; }
        __syncthreads();

        rsum0 = rsum0 * fs0 + sRsum[0][rl0] + sRsum[1][rl0];
        rsum1 = rsum1 * fs1 + sRsum[0][rl1] + sRsum[1][rl1];

        // ---- O += P V ----------------------------------------------------
#pragma unroll
        for (int s = 0; s < 8; s++) {
            uint32_t af[4];
            af[0] = sP[rl0 * PP_U32 + 8 * s + t3];
            af[1] = sP[rl1 * PP_U32 + 8 * s + t3];
            af[2] = sP[rl0 * PP_U32 + 8 * s + 4 + t3];
            af[3] = sP[rl1 * PP_U32 + 8 * s + 4 + t3];
#pragma unroll
            for (int td = 0; td < 4; td++) {
                uint32_t bfr[2];
                int dcol = 32 * wc + 8 * td + g5;
                bfr[0] = Vu[dcol * 68 + 8 * s + t3];
                bfr[1] = Vu[dcol * 68 + 8 * s + 4 + t3];
                mma_f16(oc[td], af, bfr);
            }
        }
        __syncthreads();
    }

    // ---- partial epilogue -----------------------------------------------
    float* O0 = &g_O[sp][n0 + rl0][g * 64];
    float* O1 = O0 + (size_t)8 * FF;
#pragma unroll
    for (int td = 0; td < 4; td++) {
        int c = 32 * wc + 8 * td + 2 * t3;
        *(float2*)(O0 + c) = make_float2(oc[td][0], oc[td][1]);
        *(float2*)(O1 + c) = make_float2(oc[td][2], oc[td][3]);
    }
    if (t3 == 0 && wc == 0) {
        g_Mx[sp][n0 + rl0][g] = rmax0;     g_Sm[sp][n0 + rl0][g] = rsum0;
        g_Mx[sp][n0 + rl1][g] = rmax1;     g_Sm[sp][n0 + rl1][g] = rsum1;
    }
}

// ===========================================================================
// Combine the SPLIT partial outputs.
// ===========================================================================
__global__ void __launch_bounds__(256) combine_kernel(float* __restrict__ out)
{
    int idx = blockIdx.x * 256 + threadIdx.x;     // one float2 per thread
    int n = idx / (FF / 2);
    int c = (idx - n * (FF / 2)) * 2;
    int g = c >> 6;
    float m0 = g_Mx[0][n][g], m1 = g_Mx[1][n][g];
    float Mx = fmaxf(m0, m1);
    float w0 = __expf(m0 - Mx), w1 = __expf(m1 - Mx);
    float inv = 1.f / (g_Sm[0][n][g] * w0 + g_Sm[1][n][g] * w1);
    float2 a = *(const float2*)&g_O[0][n][c];
    float2 b = *(const float2*)&g_O[1][n][c];
    *(float2*)&out[(size_t)n * FF + c] =
        make_float2((a.x * w0 + b.x * w1) * inv, (a.y * w0 + b.y * w1) * inv);
}

// ===========================================================================
extern "C" void kernel_launch(void* const* d_in, const int* in_sizes, int n_in,
                              void* d_out, int out_size)
{
    (void)in_sizes; (void)n_in; (void)out_size;
    const float* bbox     = (const float*)d_in[0];
    const float* ref_bbox = (const float*)d_in[1];
    const float* roi_feat = (const float*)d_in[2];
    const float* ref_feat = (const float*)d_in[3];
    const float* Wg_w     = (const float*)d_in[4];
    const float* Wg_b     = (const float*)d_in[5];
    const float* Wq_w     = (const float*)d_in[6];
    const float* Wq_b     = (const float*)d_in[7];
    const float* Wk_w     = (const float*)d_in[8];
    const float* Wk_b     = (const float*)d_in[9];
    const float* Wv_w     = (const float*)d_in[10];  // [16,64,1024] == [1024,1024]
    const float* Wv_b     = (const float*)d_in[11];
    const float* u        = (const float*)d_in[12];  // [16,1,64] == [1024]
    float* out = (float*)d_out;

    float* Qd; __half *Kd, *VTd;
    cudaGetSymbolAddress((void**)&Qd, g_Q);
    cudaGetSymbolAddress((void**)&Kd, g_K);
    cudaGetSymbolAddress((void**)&VTd, g_VT);

    cudaFuncSetAttribute(flash_kernel,
                         cudaFuncAttributeMaxDynamicSharedMemorySize,
                         FLASH_SMEM_BYTES);

    dim3 thr(256);

    // fused prelude: pos weights + Q proj + K|V proj, 592 blocks = 2 waves
    prelude_kernel<<<592, thr>>>(bbox, ref_bbox, roi_feat, ref_feat,
                                 Wg_w, Wg_b, Wq_w, Wq_b, Wk_w, Wk_b,
                                 Wv_w, Wv_b, u, Qd, Kd, VTd);
    // fused attention (fp16 mma, split-K over m) + combine
    flash_kernel<<<dim3(NN / 64, GG, SPLIT), thr, FLASH_SMEM_BYTES>>>();
    combine_kernel<<<NN * FF / 2 / 256, thr>>>(out);
}

// round 12
// speedup vs baseline: 1.6791x; 1.6791x over previous
#include <cuda_runtime.h>
#include <cuda_fp16.h>
#include <cstdint>
#include <cstddef>

#define NN 512
#define MM 2048
#define FF 1024
#define GG 16
#define DD 64
#define SPLIT 2

// -------- scratch ----------------------------------------------------------
__device__ float  g_Q[NN * FF];                 // Q' = roi@Wq^T + Wq_b + u (fp32)
__device__ __half g_K[MM * FF];                 // K  (fp16, [m][d])
__device__ __half g_VT[FF * MM];                // V^T (fp16, [d][m])
__device__ __half g_L[(size_t)NN * GG * MM];    // w = relu(Wg.emb+b)+1e-6 (fp16)
__device__ float  g_O[SPLIT][NN][FF];           // unnormalized partial outputs
__device__ float  g_Mx[SPLIT][NN][GG];          // partial content-score max
__device__ float  g_Sm[SPLIT][NN][GG];          // partial row sum

__constant__ float c_freq[8] = {
    100.0f,        42.16965034f, 17.78279410f, 7.498942093f,
    3.162277660f,  1.333521432f, 0.5623413252f, 0.2371373706f};

__device__ __forceinline__ uint32_t f2tf32(float f) {
    uint32_t u;
    asm("cvt.rna.tf32.f32 %0, %1;" : "=r"(u) : "f"(f));
    return u;
}

__device__ __forceinline__ uint32_t packh2(float lo, float hi) {
    uint32_t r;
    asm("cvt.rn.f16x2.f32 %0, %1, %2;" : "=r"(r) : "f"(hi), "f"(lo));
    return r;
}

__device__ __forceinline__ void mma_tf32(float* c, const uint32_t* a, const uint32_t* b) {
    asm volatile(
        "mma.sync.aligned.m16n8k8.row.col.f32.tf32.tf32.f32 "
        "{%0,%1,%2,%3}, {%4,%5,%6,%7}, {%8,%9}, {%0,%1,%2,%3};"
        : "+f"(c[0]), "+f"(c[1]), "+f"(c[2]), "+f"(c[3])
        : "r"(a[0]), "r"(a[1]), "r"(a[2]), "r"(a[3]), "r"(b[0]), "r"(b[1]));
}

__device__ __forceinline__ void mma_f16(float* c, const uint32_t* a, const uint32_t* b) {
    asm volatile(
        "mma.sync.aligned.m16n8k16.row.col.f32.f16.f16.f32 "
        "{%0,%1,%2,%3}, {%4,%5,%6,%7}, {%8,%9}, {%0,%1,%2,%3};"
        : "+f"(c[0]), "+f"(c[1]), "+f"(c[2]), "+f"(c[3])
        : "r"(a[0]), "r"(a[1]), "r"(a[2]), "r"(a[3]), "r"(b[0]), "r"(b[1]));
}

__device__ __forceinline__ void cp16(uint32_t d, const void* s) {
    asm volatile("cp.async.cg.shared.global [%0], [%1], 16;" :: "r"(d), "l"(s));
}

// ===========================================================================
// Projection GEMM body (R10's proven tf32 path; 128x128 tile, BK=16, double
// buffered). mode: 0 = fp32 [i][j]; 1 = fp16 [i][j]; 2 = fp16 T [j][i] (ld MM).
// Called exactly once from the prelude dispatcher (single 32KB smem copy).
// ===========================================================================
__device__ __noinline__ void proj_body(
    const float* __restrict__ A, int lda,
    const float* __restrict__ Bb, int ldb,
    void* __restrict__ Cb, int ldc,
    int Kdim, float alpha,
    const float* __restrict__ cb0, const float* __restrict__ cb1,
    int i0, int j0, int mode)
{
    __shared__ uint32_t sA[2][128 * 16];
    __shared__ uint32_t sB[2][128 * 16];

    const int t = threadIdx.x;
    const int w = t >> 5, lane = t & 31;
    const int g = lane >> 2, tig = lane & 3;
    const int wm = w & 1, wn = w >> 1;

    const float* aPtr[2]; int aIdx[2];
#pragma unroll
    for (int ia = 0; ia < 2; ia++) {
        int fidx = ia * 256 + t;
        int m = fidx >> 2, kq = fidx & 3;
        int ks = kq >> 1, kh = kq & 1;
        int slot = ((m >> 3) & 1) + 2 * kh;
        int tm = m >> 4, gg = m & 7;
        aPtr[ia] = A + (size_t)(i0 + m) * lda + kq * 4;
        aIdx[ia] = ((tm * 2 + ks) * 4 + slot) * 32 + ((gg ^ (slot + 4 * ks)) << 2);
    }
    const float* bPtr[2]; int bIdx[2];
#pragma unroll
    for (int ib = 0; ib < 2; ib++) {
        int fidx = ib * 256 + t;
        int n = fidx >> 2, kq = fidx & 3;
        int ks = kq >> 1, slot = kq & 1;
        int tn = n >> 3, gg = n & 7;
        bPtr[ib] = Bb + (size_t)(j0 + n) * ldb + kq * 4;
        bIdx[ib] = ((tn * 2 + ks) * 2 + slot) * 32 + ((gg ^ (slot * 4 + ks * 2)) << 2);
    }

    float acc[4][4][4];
#pragma unroll
    for (int a = 0; a < 4; a++)
#pragma unroll
        for (int b = 0; b < 4; b++)
#pragma unroll
            for (int c = 0; c < 4; c++) acc[a][b][c] = 0.f;

    const int KT = Kdim / 16;
    float4 ra[2], rb[2];

#pragma unroll
    for (int ia = 0; ia < 2; ia++) { ra[ia] = *(const float4*)(aPtr[ia]);
                                     rb[ia] = *(const float4*)(bPtr[ia]); }
#pragma unroll
    for (int ia = 0; ia < 2; ia++) {
        *(uint4*)&sA[0][aIdx[ia]] = make_uint4(f2tf32(ra[ia].x), f2tf32(ra[ia].y),
                                               f2tf32(ra[ia].z), f2tf32(ra[ia].w));
        *(uint4*)&sB[0][bIdx[ia]] = make_uint4(f2tf32(rb[ia].x), f2tf32(rb[ia].y),
                                               f2tf32(rb[ia].z), f2tf32(rb[ia].w));
    }
    __syncthreads();

    for (int kt = 0; kt < KT; kt++) {
        const int cur = kt & 1;
        if (kt + 1 < KT) {
#pragma unroll
            for (int ia = 0; ia < 2; ia++) {
                ra[ia] = *(const float4*)(aPtr[ia] + (kt + 1) * 16);
                rb[ia] = *(const float4*)(bPtr[ia] + (kt + 1) * 16);
            }
        }
#pragma unroll
        for (int ks = 0; ks < 2; ks++) {
            uint32_t af[4][4], bf[4][2];
#pragma unroll
            for (int tn = 0; tn < 4; tn++) {
                int tng = wn * 4 + tn;
                int base = ((tng * 2 + ks) * 2) * 32;
                bf[tn][0] = sB[cur][base + ((g ^ (ks * 2)) << 2) + tig];
                bf[tn][1] = sB[cur][base + 32 + ((g ^ (4 + ks * 2)) << 2) + tig];
            }
#pragma unroll
            for (int tm = 0; tm < 4; tm++) {
                int tmg = wm * 4 + tm;
                int base = ((tmg * 2 + ks) * 4) * 32;
#pragma unroll
                for (int s = 0; s < 4; s++)
                    af[tm][s] = sA[cur][base + s * 32 + ((g ^ (s + 4 * ks)) << 2) + tig];
            }
#pragma unroll
            for (int tm = 0; tm < 4; tm++)
#pragma unroll
                for (int tn = 0; tn < 4; tn++)
                    mma_tf32(acc[tm][tn], af[tm], bf[tn]);
        }
        if (kt + 1 < KT) {
            const int nxt = cur ^ 1;
#pragma unroll
            for (int ia = 0; ia < 2; ia++) {
                *(uint4*)&sA[nxt][aIdx[ia]] = make_uint4(f2tf32(ra[ia].x), f2tf32(ra[ia].y),
                                                         f2tf32(ra[ia].z), f2tf32(ra[ia].w));
                *(uint4*)&sB[nxt][bIdx[ia]] = make_uint4(f2tf32(rb[ia].x), f2tf32(rb[ia].y),
                                                         f2tf32(rb[ia].z), f2tf32(rb[ia].w));
            }
        }
        __syncthreads();
    }

#pragma unroll
    for (int tm = 0; tm < 4; tm++) {
        int r = i0 + wm * 64 + tm * 16 + g;
#pragma unroll
        for (int tn = 0; tn < 4; tn++) {
            int c = j0 + wn * 32 + tn * 8 + tig * 2;
            float b0 = 0.f, b1 = 0.f;
            if (cb0) { b0 += cb0[c]; b1 += cb0[c + 1]; }
            if (cb1) { b0 += cb1[c]; b1 += cb1[c + 1]; }
            float v0 = acc[tm][tn][0] * alpha + b0;
            float v1 = acc[tm][tn][1] * alpha + b1;
            float v2 = acc[tm][tn][2] * alpha + b0;
            float v3 = acc[tm][tn][3] * alpha + b1;
            if (mode == 0) {
                float* Cf = (float*)Cb;
                *(float2*)(Cf + (size_t)r * ldc + c) = make_float2(v0, v1);
                *(float2*)(Cf + (size_t)(r + 8) * ldc + c) = make_float2(v2, v3);
            } else if (mode == 1) {
                __half* Ch = (__half*)Cb;
                *(uint32_t*)(Ch + (size_t)r * ldc + c) = packh2(v0, v1);
                *(uint32_t*)(Ch + (size_t)(r + 8) * ldc + c) = packh2(v2, v3);
            } else {
                __half* Ch = (__half*)Cb;        // [j][i], stride MM
                Ch[(size_t)c * MM + r]           = __float2half_rn(v0);
                Ch[(size_t)(c + 1) * MM + r]     = __float2half_rn(v1);
                Ch[(size_t)c * MM + r + 8]       = __float2half_rn(v2);
                Ch[(size_t)(c + 1) * MM + r + 8] = __float2half_rn(v3);
            }
        }
    }
}

// ===========================================================================
// pos body: w[n][g][m] = relu(emb(n,m,:)·Wg[g,:]+b) + 1e-6, fp16 out.
// One block covers HALF the m-range (mh in {0,1}) for one n: finer quanta
// for wave packing. Numerics identical to the full-range version.
// ===========================================================================
__device__ __noinline__ void pos_body(
    int n, int mh,
    const float* __restrict__ bbox, const float* __restrict__ ref_bbox,
    const float* __restrict__ Wg_w, const float* __restrict__ Wg_b)
{
    const int t = threadIdx.x;
    const int w = t >> 5, lane = t & 31;
    const int g5 = lane >> 2, t3 = lane & 3;

    float x0 = bbox[n * 4 + 0], y0 = bbox[n * 4 + 1];
    float x1 = bbox[n * 4 + 2], y1 = bbox[n * 4 + 3];
    float bw = x1 - x0 + 1.f, bh = y1 - y0 + 1.f;
    float cx = 0.5f * (x0 + x1), cy = 0.5f * (y0 + y1);
    float iw = 1.f / bw, ih = 1.f / bh;
    float lw = __logf(bw), lh = __logf(bh);

    uint32_t breg[2][8][2];
#pragma unroll
    for (int tt = 0; tt < 2; tt++)
#pragma unroll
        for (int s = 0; s < 8; s++) {
            breg[tt][s][0] = f2tf32(Wg_w[(8 * tt + g5) * 64 + 8 * s + t3]);
            breg[tt][s][1] = f2tf32(Wg_w[(8 * tt + g5) * 64 + 8 * s + 4 + t3]);
        }
    float bias[2][2];
#pragma unroll
    for (int tt = 0; tt < 2; tt++) {
        bias[tt][0] = Wg_b[8 * tt + 2 * t3];
        bias[tt][1] = Wg_b[8 * tt + 2 * t3 + 1];
    }
    const float fr0 = c_freq[t3], fr1 = c_freq[t3 + 4];

    __half* Lpn = g_L + (size_t)n * GG * MM;

    for (int it = 0; it < 8; it++) {
        const int mbase = (mh * 64 + it * 8 + w) * 16;
        const int m0p = mbase + g5, m1p = m0p + 8;

        float4 rb0 = *(const float4*)(ref_bbox + (size_t)m0p * 4);
        float4 rb1 = *(const float4*)(ref_bbox + (size_t)m1p * 4);
        float p0[4], p1[4];
        {
            float wr = rb0.z - rb0.x + 1.f, hr = rb0.w - rb0.y + 1.f;
            float cxr = 0.5f * (rb0.x + rb0.z), cyr = 0.5f * (rb0.y + rb0.w);
            p0[0] = __logf(fabsf((cx - cxr) * iw) + 1e-3f);
            p0[1] = __logf(fabsf((cy - cyr) * ih) + 1e-3f);
            p0[2] = lw - __logf(wr);
            p0[3] = lh - __logf(hr);
        }
        {
            float wr = rb1.z - rb1.x + 1.f, hr = rb1.w - rb1.y + 1.f;
            float cxr = 0.5f * (rb1.x + rb1.z), cyr = 0.5f * (rb1.y + rb1.w);
            p1[0] = __logf(fabsf((cx - cxr) * iw) + 1e-3f);
            p1[1] = __logf(fabsf((cy - cyr) * ih) + 1e-3f);
            p1[2] = lw - __logf(wr);
            p1[3] = lh - __logf(hr);
        }

        float ct[2][4];
#pragma unroll
        for (int tt = 0; tt < 2; tt++)
#pragma unroll
            for (int j = 0; j < 4; j++) ct[tt][j] = 0.f;

#pragma unroll
        for (int c = 0; c < 4; c++) {
            float s00, c00, s01, c01, s10, c10, s11, c11;
            __sincosf(p0[c] * fr0, &s00, &c00);
            __sincosf(p0[c] * fr1, &s01, &c01);
            __sincosf(p1[c] * fr0, &s10, &c10);
            __sincosf(p1[c] * fr1, &s11, &c11);
            uint32_t asin_[4] = {f2tf32(s00), f2tf32(s10), f2tf32(s01), f2tf32(s11)};
            uint32_t acos_[4] = {f2tf32(c00), f2tf32(c10), f2tf32(c01), f2tf32(c11)};
            mma_tf32(ct[0], asin_, breg[0][2 * c]);
            mma_tf32(ct[1], asin_, breg[1][2 * c]);
            mma_tf32(ct[0], acos_, breg[0][2 * c + 1]);
            mma_tf32(ct[1], acos_, breg[1][2 * c + 1]);
        }

#pragma unroll
        for (int tt = 0; tt < 2; tt++) {
            int gc = 8 * tt + 2 * t3;
            float v0 = fmaxf(ct[tt][0] + bias[tt][0], 0.f) + 1e-6f;
            float v1 = fmaxf(ct[tt][1] + bias[tt][1], 0.f) + 1e-6f;
            float v2 = fmaxf(ct[tt][2] + bias[tt][0], 0.f) + 1e-6f;
            float v3 = fmaxf(ct[tt][3] + bias[tt][1], 0.f) + 1e-6f;
            Lpn[(size_t)gc * MM + m0p]       = __float2half_rn(v0);
            Lpn[(size_t)(gc + 1) * MM + m0p] = __float2half_rn(v1);
            Lpn[(size_t)gc * MM + m1p]       = __float2half_rn(v2);
            Lpn[(size_t)(gc + 1) * MM + m1p] = __float2half_rn(v3);
        }
    }
}

// ===========================================================================
// Prelude dispatcher: 1312 blocks, proj/pos interleaved like R10 but with
// half-m pos quanta (1024 pos chunks):
//   bid < 576: even -> proj(bid/2) [0..287], odd -> pos chunk bid/2 [0..287]
//   bid >= 576: pos chunk (bid - 288)        [288..1023]
// pos chunk id c: n = c >> 1, mh = c & 1.
// proj id p: p < 32 -> Q projection (grid 8x4); else p-32 -> K|V (grid 16x16).
// ===========================================================================
__global__ void __launch_bounds__(256) prelude_kernel(
    const float* __restrict__ bbox, const float* __restrict__ ref_bbox,
    const float* __restrict__ roi_feat, const float* __restrict__ ref_feat,
    const float* __restrict__ Wg_w, const float* __restrict__ Wg_b,
    const float* __restrict__ Wq_w, const float* __restrict__ Wq_b,
    const float* __restrict__ Wk_w, const float* __restrict__ Wk_b,
    const float* __restrict__ Wv_w, const float* __restrict__ Wv_b,
    const float* __restrict__ u,
    float* __restrict__ Qd, __half* __restrict__ Kd, __half* __restrict__ VTd)
{
    const int bid = blockIdx.x;
    int proj = -1, posc = -1;
    if (bid < 576) {
        if ((bid & 1) == 0) proj = bid >> 1;
        else posc = bid >> 1;
    } else {
        posc = bid - 288;
    }

    if (posc >= 0) {
        pos_body(posc >> 1, posc & 1, bbox, ref_bbox, Wg_w, Wg_b);
        return;
    }

    // resolve projection arguments, single proj_body call (one smem copy)
    const float *A, *B, *cb0, *cb1 = nullptr;
    void* C;
    int i0, j0, mode;
    if (proj < 32) {                 // Q projection: grid 8 x 4 over (FF, NN)
        int bx = proj & 7, by = proj >> 3;
        A = roi_feat; B = Wq_w; C = Qd; cb0 = Wq_b; cb1 = u;
        i0 = by * 128; j0 = bx * 128; mode = 0;
    } else {                         // K|V projection: grid 16 x 16 over (2FF, MM)
        int p = proj - 32;
        int bx = p & 15, by = p >> 4;
        A = ref_feat;
        i0 = by * 128; j0 = bx * 128;
        if (j0 < FF) { B = Wk_w; C = Kd; cb0 = Wk_b; mode = 1; }
        else         { B = Wv_w; C = VTd; cb0 = Wv_b; mode = 2; j0 -= FF; }
    }
    proj_body(A, FF, B, FF, C, FF, FF, 1.f, cb0, cb1, i0, j0, mode);
}

// ===========================================================================
// Flash attention (fp16 mma, R8/R10 version): block = (n-tile 64, head g,
// split). Q staged through smem. 2 blocks/SM.
// ===========================================================================
#define KB_U32 (128 * 36)
#define VB_U32 (64 * 68)
#define PP_U32 68
#define FLASH_SMEM_BYTES ((2 * KB_U32 + 2 * VB_U32 + 64 * PP_U32) * 4)
#define FL_TILES ((MM / SPLIT) / 128)   // 8

__global__ void __launch_bounds__(256, 2) flash_kernel()
{
    extern __shared__ uint32_t smem[];
    uint32_t* sK = smem;                           // [2][128][36] u32
    uint32_t* sV = smem + 2 * KB_U32;              // [2][64][68] u32
    uint32_t* sP = smem + 2 * KB_U32 + 2 * VB_U32; // [64][68] u32

    __shared__ float sRmax[2][64];
    __shared__ float sRsum[2][64];

    const int t = threadIdx.x;
    const int w = t >> 5, lane = t & 31;
    const int g5 = lane >> 2, t3 = lane & 3;
    const int wr = w & 3, wc = w >> 2;
    const int n0 = blockIdx.x * 64;
    const int g = blockIdx.y;
    const int sp = blockIdx.z;
    const int m_base = sp * (MM / SPLIT);

    const uint32_t kb = (uint32_t)__cvta_generic_to_shared(sK);
    const uint32_t vb = (uint32_t)__cvta_generic_to_shared(sV);

    // ---- Q tile (64x64 fp32) -> staging -> packed fp16 fragments --------
    {
        float* sPf = (float*)sP;                 // pitch 68 floats
#pragma unroll
        for (int i = 0; i < 4; i++) {
            int f = t + i * 256;
            int row = f >> 4, c4 = (f & 15) << 2;
            *(float4*)&sPf[row * 68 + c4] =
                *(const float4*)(g_Q + (size_t)(n0 + row) * FF + g * 64 + c4);
        }
    }
    __syncthreads();
    const int rl0 = 16 * wr + g5, rl1 = rl0 + 8;
    uint32_t qf[4][4];
    {
        const float* sPf = (const float*)sP;
        int r = 16 * wr + g5;
#pragma unroll
        for (int s = 0; s < 4; s++) {
            float2 x0 = *(const float2*)&sPf[r * 68 + 16 * s + 2 * t3];
            float2 x1 = *(const float2*)&sPf[(r + 8) * 68 + 16 * s + 2 * t3];
            float2 x2 = *(const float2*)&sPf[r * 68 + 16 * s + 2 * t3 + 8];
            float2 x3 = *(const float2*)&sPf[(r + 8) * 68 + 16 * s + 2 * t3 + 8];
            qf[s][0] = packh2(x0.x, x0.y);
            qf[s][1] = packh2(x1.x, x1.y);
            qf[s][2] = packh2(x2.x, x2.y);
            qf[s][3] = packh2(x3.x, x3.y);
        }
    }

    // ---- K / V^T tile loaders (cp.async, fp16) --------------------------
    auto load_kv = [&](int buf, int m0) {
#pragma unroll
        for (int i = 0; i < 4; i++) {            // K: 128 rows x 128B
            int f = t + i * 256;
            int row = f >> 3, h8 = (f & 7) * 8;
            cp16(kb + (uint32_t)((buf * KB_U32 + row * 36) * 4 + h8 * 2),
                 g_K + (size_t)(m0 + row) * FF + g * 64 + h8);
        }
#pragma unroll
        for (int i = 0; i < 4; i++) {            // VT: 64 rows x 256B
            int f = t + i * 256;
            int row = f >> 4, h8 = (f & 15) * 8;
            cp16(vb + (uint32_t)((buf * VB_U32 + row * 68) * 4 + h8 * 2),
                 g_VT + (size_t)(g * 64 + row) * MM + m0 + h8);
        }
        asm volatile("cp.async.commit_group;");
    };

    load_kv(0, m_base);
    __syncthreads();   // Q staging in sP consumed before first P write

    float rmax0 = -1e30f, rmax1 = -1e30f, rsum0 = 0.f, rsum1 = 0.f;
    float oc[4][4];
#pragma unroll
    for (int a = 0; a < 4; a++)
#pragma unroll
        for (int b = 0; b < 4; b++) oc[a][b] = 0.f;

    for (int mt = 0; mt < FL_TILES; mt++) {
        if (mt + 1 < FL_TILES) {
            load_kv((mt + 1) & 1, m_base + (mt + 1) * 128);
            asm volatile("cp.async.wait_group 1;");
        } else {
            asm volatile("cp.async.wait_group 0;");
        }
        __syncthreads();

        const uint32_t* Ku = sK + (mt & 1) * KB_U32;
        const uint32_t* Vu = sV + (mt & 1) * VB_U32;

        // pos weights (fp16, multiplicative)
        __half2 lp0[8], lp1[8];
        {
            size_t base0 = ((size_t)(n0 + rl0) * GG + g) * MM
                         + m_base + mt * 128 + 64 * wc + 2 * t3;
            size_t base1 = base0 + (size_t)8 * GG * MM;
#pragma unroll
            for (int tn = 0; tn < 8; tn++) {
                lp0[tn] = *(const __half2*)(g_L + base0 + 8 * tn);
                lp1[tn] = *(const __half2*)(g_L + base1 + 8 * tn);
            }
        }

        // ---- S = Q K^T ---------------------------------------------------
        float sc[8][4];
#pragma unroll
        for (int a = 0; a < 8; a++)
#pragma unroll
            for (int b = 0; b < 4; b++) sc[a][b] = 0.f;
#pragma unroll
        for (int s = 0; s < 4; s++)
#pragma unroll
            for (int tn = 0; tn < 8; tn++) {
                uint32_t bfr[2];
                int mr = 64 * wc + 8 * tn + g5;
                bfr[0] = Ku[mr * 36 + 8 * s + t3];
                bfr[1] = Ku[mr * 36 + 8 * s + 4 + t3];
                mma_f16(sc[tn], qf[s], bfr);
            }

        // content-score max
        float pm0 = -1e30f, pm1 = -1e30f;
#pragma unroll
        for (int tn = 0; tn < 8; tn++) {
            sc[tn][0] *= 0.125f;
            sc[tn][1] *= 0.125f;
            sc[tn][2] *= 0.125f;
            sc[tn][3] *= 0.125f;
            pm0 = fmaxf(pm0, fmaxf(sc[tn][0], sc[tn][1]));
            pm1 = fmaxf(pm1, fmaxf(sc[tn][2], sc[tn][3]));
        }
        pm0 = fmaxf(pm0, __shfl_xor_sync(~0u, pm0, 1));
        pm0 = fmaxf(pm0, __shfl_xor_sync(~0u, pm0, 2));
        pm1 = fmaxf(pm1, __shfl_xor_sync(~0u, pm1, 1));
        pm1 = fmaxf(pm1, __shfl_xor_sync(~0u, pm1, 2));
        if (t3 == 0) { sRmax[wc][rl0] = pm0; sRmax[wc][rl1] = pm1; }
        __syncthreads();

        float nm0 = fmaxf(rmax0, fmaxf(sRmax[0][rl0], sRmax[1][rl0]));
        float nm1 = fmaxf(rmax1, fmaxf(sRmax[0][rl1], sRmax[1][rl1]));
        float fs0 = __expf(rmax0 - nm0);
        float fs1 = __expf(rmax1 - nm1);
        rmax0 = nm0; rmax1 = nm1;
#pragma unroll
        for (int td = 0; td < 4; td++) {
            oc[td][0] *= fs0; oc[td][1] *= fs0;
            oc[td][2] *= fs1; oc[td][3] *= fs1;
        }

        // ---- P = w * exp(a - max), fp16 into sP -------------------------
        float ps0 = 0.f, ps1 = 0.f;
#pragma unroll
        for (int tn = 0; tn < 8; tn++) {
            float2 w0 = __half22float2(lp0[tn]);
            float2 w1 = __half22float2(lp1[tn]);
            float p0 = w0.x * __expf(sc[tn][0] - nm0);
            float p1 = w0.y * __expf(sc[tn][1] - nm0);
            float p2 = w1.x * __expf(sc[tn][2] - nm1);
            float p3 = w1.y * __expf(sc[tn][3] - nm1);
            ps0 += p0 + p1; ps1 += p2 + p3;
            int colq = 32 * wc + 4 * tn + t3;
            sP[rl0 * PP_U32 + colq] = packh2(p0, p1);
            sP[rl1 * PP_U32 + colq] = packh2(p2, p3);
        }
        ps0 += __shfl_xor_sync(~0u, ps0, 1);
        ps0 += __shfl_xor_sync(~0u, ps0, 2);
        ps1 += __shfl_xor_sync(~0u, ps1, 1);
        ps1 += __shfl_xor_sync(~0u, ps1, 2);
        if (t3 == 0) { sRsum[wc][rl0] = ps0; sRsum[wc][rl1] = ps1; }
        __syncthreads();

        rsum0 = rsum0 * fs0 + sRsum[0][rl0] + sRsum[1][rl0];
        rsum1 = rsum1 * fs1 + sRsum[0][rl1] + sRsum[1][rl1];

        // ---- O += P V ----------------------------------------------------
#pragma unroll
        for (int s = 0; s < 8; s++) {
            uint32_t af[4];
            af[0] = sP[rl0 * PP_U32 + 8 * s + t3];
            af[1] = sP[rl1 * PP_U32 + 8 * s + t3];
            af[2] = sP[rl0 * PP_U32 + 8 * s + 4 + t3];
            af[3] = sP[rl1 * PP_U32 + 8 * s + 4 + t3];
#pragma unroll
            for (int td = 0; td < 4; td++) {
                uint32_t bfr[2];
                int dcol = 32 * wc + 8 * td + g5;
                bfr[0] = Vu[dcol * 68 + 8 * s + t3];
                bfr[1] = Vu[dcol * 68 + 8 * s + 4 + t3];
                mma_f16(oc[td], af, bfr);
            }
        }
        __syncthreads();
    }

    // ---- partial epilogue -----------------------------------------------
    float* O0 = &g_O[sp][n0 + rl0][g * 64];
    float* O1 = O0 + (size_t)8 * FF;
#pragma unroll
    for (int td = 0; td < 4; td++) {
        int c = 32 * wc + 8 * td + 2 * t3;
        *(float2*)(O0 + c) = make_float2(oc[td][0], oc[td][1]);
        *(float2*)(O1 + c) = make_float2(oc[td][2], oc[td][3]);
    }
    if (t3 == 0 && wc == 0) {
        g_Mx[sp][n0 + rl0][g] = rmax0;     g_Sm[sp][n0 + rl0][g] = rsum0;
        g_Mx[sp][n0 + rl1][g] = rmax1;     g_Sm[sp][n0 + rl1][g] = rsum1;
    }
}

// ===========================================================================
// Combine the SPLIT partial outputs.
// ===========================================================================
__global__ void __launch_bounds__(256) combine_kernel(float* __restrict__ out)
{
    int idx = blockIdx.x * 256 + threadIdx.x;     // one float2 per thread
    int n = idx / (FF / 2);
    int c = (idx - n * (FF / 2)) * 2;
    int g = c >> 6;
    float m0 = g_Mx[0][n][g], m1 = g_Mx[1][n][g];
    float Mx = fmaxf(m0, m1);
    float w0 = __expf(m0 - Mx), w1 = __expf(m1 - Mx);
    float inv = 1.f / (g_Sm[0][n][g] * w0 + g_Sm[1][n][g] * w1);
    float2 a = *(const float2*)&g_O[0][n][c];
    float2 b = *(const float2*)&g_O[1][n][c];
    *(float2*)&out[(size_t)n * FF + c] =
        make_float2((a.x * w0 + b.x * w1) * inv, (a.y * w0 + b.y * w1) * inv);
}

// ===========================================================================
extern "C" void kernel_launch(void* const* d_in, const int* in_sizes, int n_in,
                              void* d_out, int out_size)
{
    (void)in_sizes; (void)n_in; (void)out_size;
    const float* bbox     = (const float*)d_in[0];
    const float* ref_bbox = (const float*)d_in[1];
    const float* roi_feat = (const float*)d_in[2];
    const float* ref_feat = (const float*)d_in[3];
    const float* Wg_w     = (const float*)d_in[4];
    const float* Wg_b     = (const float*)d_in[5];
    const float* Wq_w     = (const float*)d_in[6];
    const float* Wq_b     = (const float*)d_in[7];
    const float* Wk_w     = (const float*)d_in[8];
    const float* Wk_b     = (const float*)d_in[9];
    const float* Wv_w     = (const float*)d_in[10];  // [16,64,1024] == [1024,1024]
    const float* Wv_b     = (const float*)d_in[11];
    const float* u        = (const float*)d_in[12];  // [16,1,64] == [1024]
    float* out = (float*)d_out;

    float* Qd; __half *Kd, *VTd;
    cudaGetSymbolAddress((void**)&Qd, g_Q);
    cudaGetSymbolAddress((void**)&Kd, g_K);
    cudaGetSymbolAddress((void**)&VTd, g_VT);

    cudaFuncSetAttribute(flash_kernel,
                         cudaFuncAttributeMaxDynamicSharedMemorySize,
                         FLASH_SMEM_BYTES);

    dim3 thr(256);

    // fused prelude: pos weights (half-m quanta) + Q proj + K|V proj
    prelude_kernel<<<1312, thr>>>(bbox, ref_bbox, roi_feat, ref_feat,
                                  Wg_w, Wg_b, Wq_w, Wq_b, Wk_w, Wk_b,
                                  Wv_w, Wv_b, u, Qd, Kd, VTd);
    // fused attention (fp16 mma, split-K over m) + combine
    flash_kernel<<<dim3(NN / 64, GG, SPLIT), thr, FLASH_SMEM_BYTES>>>();
    combine_kernel<<<NN * FF / 2 / 256, thr>>>(out);
}

// round 13
// speedup vs baseline: 1.8832x; 1.1216x over previous
#include <cuda_runtime.h>
#include <cuda_fp16.h>
#include <cstdint>
#include <cstddef>

#define NN 512
#define MM 2048
#define FF 1024
#define GG 16
#define DD 64
#define SPLIT 2

// -------- scratch ----------------------------------------------------------
__device__ float  g_Q[NN * FF];                 // Q' = 0.125*(roi@Wq^T + b + u) (fp32)
__device__ __half g_K[MM * FF];                 // K  (fp16, [m][d])
__device__ __half g_VT[FF * MM];                // V^T (fp16, [d][m])
__device__ __half g_L[(size_t)NN * GG * MM];    // w = relu(Wg.emb+b)+1e-6 (fp16)
__device__ float  g_O[SPLIT][NN][FF];           // unnormalized partial outputs
__device__ float  g_Mx[SPLIT][NN][GG];          // partial content-score max
__device__ float  g_Sm[SPLIT][NN][GG];          // partial row sum

__constant__ float c_freq[8] = {
    100.0f,        42.16965034f, 17.78279410f, 7.498942093f,
    3.162277660f,  1.333521432f, 0.5623413252f, 0.2371373706f};

__device__ __forceinline__ uint32_t f2tf32(float f) {
    uint32_t u;
    asm("cvt.rna.tf32.f32 %0, %1;" : "=r"(u) : "f"(f));
    return u;
}

__device__ __forceinline__ uint32_t packh2(float lo, float hi) {
    uint32_t r;
    asm("cvt.rn.f16x2.f32 %0, %1, %2;" : "=r"(r) : "f"(hi), "f"(lo));
    return r;
}

__device__ __forceinline__ void mma_tf32(float* c, const uint32_t* a, const uint32_t* b) {
    asm volatile(
        "mma.sync.aligned.m16n8k8.row.col.f32.tf32.tf32.f32 "
        "{%0,%1,%2,%3}, {%4,%5,%6,%7}, {%8,%9}, {%0,%1,%2,%3};"
        : "+f"(c[0]), "+f"(c[1]), "+f"(c[2]), "+f"(c[3])
        : "r"(a[0]), "r"(a[1]), "r"(a[2]), "r"(a[3]), "r"(b[0]), "r"(b[1]));
}

__device__ __forceinline__ void mma_f16(float* c, const uint32_t* a, const uint32_t* b) {
    asm volatile(
        "mma.sync.aligned.m16n8k16.row.col.f32.f16.f16.f32 "
        "{%0,%1,%2,%3}, {%4,%5,%6,%7}, {%8,%9}, {%0,%1,%2,%3};"
        : "+f"(c[0]), "+f"(c[1]), "+f"(c[2]), "+f"(c[3])
        : "r"(a[0]), "r"(a[1]), "r"(a[2]), "r"(a[3]), "r"(b[0]), "r"(b[1]));
}

__device__ __forceinline__ void cp16(uint32_t d, const void* s) {
    asm volatile("cp.async.cg.shared.global [%0], [%1], 16;" :: "r"(d), "l"(s));
}

// ===========================================================================
// Projection GEMM body, fp16 datapath (mma.m16n8k16, 128x128 tile, BK=16,
// double buffered). fp32->f16x2 pack at smem store; fp32 accumulate.
// smem pitch 12 u32 per 16-half row: fragment loads bank-conflict-free
// (banks 12*g5+t3 mod 32 all distinct); uint2 stores 2-way only.
// mode: 0 = fp32 [i][j]; 1 = fp16 [i][j]; 2 = fp16 T [j][i] (ld MM).
// Epilogue: v = (acc + bias) * alpha  (alpha = exact power of two).
// ===========================================================================
__device__ __noinline__ void proj_body(
    const float* __restrict__ A, int lda,
    const float* __restrict__ Bb, int ldb,
    void* __restrict__ Cb, int ldc,
    int Kdim, float alpha,
    const float* __restrict__ cb0, const float* __restrict__ cb1,
    int i0, int j0, int mode)
{
    __shared__ uint32_t sA[2][128 * 12];
    __shared__ uint32_t sB[2][128 * 12];

    const int t = threadIdx.x;
    const int w = t >> 5, lane = t & 31;
    const int g = lane >> 2, tig = lane & 3;
    const int wm = w & 1, wn = w >> 1;          // 2 x 4 warp grid

    // loader precompute: 2 float4 per thread per tile for each matrix
    const float* aPtr[2]; int aIdx[2];
    const float* bPtr[2]; int bIdx[2];
#pragma unroll
    for (int ia = 0; ia < 2; ia++) {
        int fidx = ia * 256 + t;
        int row = fidx >> 2, kq = fidx & 3;
        aPtr[ia] = A + (size_t)(i0 + row) * lda + kq * 4;
        bPtr[ia] = Bb + (size_t)(j0 + row) * ldb + kq * 4;
        aIdx[ia] = row * 12 + 2 * kq;
        bIdx[ia] = row * 12 + 2 * kq;
    }

    float acc[4][4][4];
#pragma unroll
    for (int a = 0; a < 4; a++)
#pragma unroll
        for (int b = 0; b < 4; b++)
#pragma unroll
            for (int c = 0; c < 4; c++) acc[a][b][c] = 0.f;

    const int KT = Kdim / 16;
    float4 ra[2], rb[2];

    // prologue: tile 0
#pragma unroll
    for (int ia = 0; ia < 2; ia++) { ra[ia] = *(const float4*)(aPtr[ia]);
                                     rb[ia] = *(const float4*)(bPtr[ia]); }
#pragma unroll
    for (int ia = 0; ia < 2; ia++) {
        *(uint2*)&sA[0][aIdx[ia]] = make_uint2(packh2(ra[ia].x, ra[ia].y),
                                               packh2(ra[ia].z, ra[ia].w));
        *(uint2*)&sB[0][bIdx[ia]] = make_uint2(packh2(rb[ia].x, rb[ia].y),
                                               packh2(rb[ia].z, rb[ia].w));
    }
    __syncthreads();

    for (int kt = 0; kt < KT; kt++) {
        const int cur = kt & 1;
        if (kt + 1 < KT) {
#pragma unroll
            for (int ia = 0; ia < 2; ia++) {
                ra[ia] = *(const float4*)(aPtr[ia] + (kt + 1) * 16);
                rb[ia] = *(const float4*)(bPtr[ia] + (kt + 1) * 16);
            }
        }
        const uint32_t* Sa = sA[cur];
        const uint32_t* Sb = sB[cur];
        uint32_t af[4][4], bf[4][2];
#pragma unroll
        for (int tn = 0; tn < 4; tn++) {
            int Cr = (wn * 32 + tn * 8 + g) * 12;
            bf[tn][0] = Sb[Cr + tig];
            bf[tn][1] = Sb[Cr + 4 + tig];
        }
#pragma unroll
        for (int tm = 0; tm < 4; tm++) {
            int R0 = (wm * 64 + tm * 16 + g) * 12;
            af[tm][0] = Sa[R0 + tig];
            af[tm][1] = Sa[R0 + 96 + tig];       // +8 rows
            af[tm][2] = Sa[R0 + 4 + tig];
            af[tm][3] = Sa[R0 + 96 + 4 + tig];
        }
#pragma unroll
        for (int tm = 0; tm < 4; tm++)
#pragma unroll
            for (int tn = 0; tn < 4; tn++)
                mma_f16(acc[tm][tn], af[tm], bf[tn]);

        if (kt + 1 < KT) {
            const int nxt = cur ^ 1;
#pragma unroll
            for (int ia = 0; ia < 2; ia++) {
                *(uint2*)&sA[nxt][aIdx[ia]] = make_uint2(packh2(ra[ia].x, ra[ia].y),
                                                         packh2(ra[ia].z, ra[ia].w));
                *(uint2*)&sB[nxt][bIdx[ia]] = make_uint2(packh2(rb[ia].x, rb[ia].y),
                                                         packh2(rb[ia].z, rb[ia].w));
            }
        }
        __syncthreads();
    }

    // ---- epilogue: v = (acc + bias) * alpha ------------------------------
#pragma unroll
    for (int tm = 0; tm < 4; tm++) {
        int r = i0 + wm * 64 + tm * 16 + g;
#pragma unroll
        for (int tn = 0; tn < 4; tn++) {
            int c = j0 + wn * 32 + tn * 8 + tig * 2;
            float b0 = 0.f, b1 = 0.f;
            if (cb0) { b0 += cb0[c]; b1 += cb0[c + 1]; }
            if (cb1) { b0 += cb1[c]; b1 += cb1[c + 1]; }
            float v0 = (acc[tm][tn][0] + b0) * alpha;
            float v1 = (acc[tm][tn][1] + b1) * alpha;
            float v2 = (acc[tm][tn][2] + b0) * alpha;
            float v3 = (acc[tm][tn][3] + b1) * alpha;
            if (mode == 0) {
                float* Cf = (float*)Cb;
                *(float2*)(Cf + (size_t)r * ldc + c) = make_float2(v0, v1);
                *(float2*)(Cf + (size_t)(r + 8) * ldc + c) = make_float2(v2, v3);
            } else if (mode == 1) {
                __half* Ch = (__half*)Cb;
                *(uint32_t*)(Ch + (size_t)r * ldc + c) = packh2(v0, v1);
                *(uint32_t*)(Ch + (size_t)(r + 8) * ldc + c) = packh2(v2, v3);
            } else {
                __half* Ch = (__half*)Cb;        // [j][i], stride MM
                Ch[(size_t)c * MM + r]           = __float2half_rn(v0);
                Ch[(size_t)(c + 1) * MM + r]     = __float2half_rn(v1);
                Ch[(size_t)c * MM + r + 8]       = __float2half_rn(v2);
                Ch[(size_t)(c + 1) * MM + r + 8] = __float2half_rn(v3);
            }
        }
    }
}

// ===========================================================================
// pos body: w[n][g][m] = relu(emb(n,m,:)·Wg[g,:]+b) + 1e-6, fp16 out.
// One block covers HALF the m-range (mh in {0,1}) for one n.
// ===========================================================================
__device__ __noinline__ void pos_body(
    int n, int mh,
    const float* __restrict__ bbox, const float* __restrict__ ref_bbox,
    const float* __restrict__ Wg_w, const float* __restrict__ Wg_b)
{
    const int t = threadIdx.x;
    const int w = t >> 5, lane = t & 31;
    const int g5 = lane >> 2, t3 = lane & 3;

    float x0 = bbox[n * 4 + 0], y0 = bbox[n * 4 + 1];
    float x1 = bbox[n * 4 + 2], y1 = bbox[n * 4 + 3];
    float bw = x1 - x0 + 1.f, bh = y1 - y0 + 1.f;
    float cx = 0.5f * (x0 + x1), cy = 0.5f * (y0 + y1);
    float iw = 1.f / bw, ih = 1.f / bh;
    float lw = __logf(bw), lh = __logf(bh);

    uint32_t breg[2][8][2];
#pragma unroll
    for (int tt = 0; tt < 2; tt++)
#pragma unroll
        for (int s = 0; s < 8; s++) {
            breg[tt][s][0] = f2tf32(Wg_w[(8 * tt + g5) * 64 + 8 * s + t3]);
            breg[tt][s][1] = f2tf32(Wg_w[(8 * tt + g5) * 64 + 8 * s + 4 + t3]);
        }
    float bias[2][2];
#pragma unroll
    for (int tt = 0; tt < 2; tt++) {
        bias[tt][0] = Wg_b[8 * tt + 2 * t3];
        bias[tt][1] = Wg_b[8 * tt + 2 * t3 + 1];
    }
    const float fr0 = c_freq[t3], fr1 = c_freq[t3 + 4];

    __half* Lpn = g_L + (size_t)n * GG * MM;

    for (int it = 0; it < 8; it++) {
        const int mbase = (mh * 64 + it * 8 + w) * 16;
        const int m0p = mbase + g5, m1p = m0p + 8;

        float4 rb0 = *(const float4*)(ref_bbox + (size_t)m0p * 4);
        float4 rb1 = *(const float4*)(ref_bbox + (size_t)m1p * 4);
        float p0[4], p1[4];
        {
            float wr = rb0.z - rb0.x + 1.f, hr = rb0.w - rb0.y + 1.f;
            float cxr = 0.5f * (rb0.x + rb0.z), cyr = 0.5f * (rb0.y + rb0.w);
            p0[0] = __logf(fabsf((cx - cxr) * iw) + 1e-3f);
            p0[1] = __logf(fabsf((cy - cyr) * ih) + 1e-3f);
            p0[2] = lw - __logf(wr);
            p0[3] = lh - __logf(hr);
        }
        {
            float wr = rb1.z - rb1.x + 1.f, hr = rb1.w - rb1.y + 1.f;
            float cxr = 0.5f * (rb1.x + rb1.z), cyr = 0.5f * (rb1.y + rb1.w);
            p1[0] = __logf(fabsf((cx - cxr) * iw) + 1e-3f);
            p1[1] = __logf(fabsf((cy - cyr) * ih) + 1e-3f);
            p1[2] = lw - __logf(wr);
            p1[3] = lh - __logf(hr);
        }

        float ct[2][4];
#pragma unroll
        for (int tt = 0; tt < 2; tt++)
#pragma unroll
            for (int j = 0; j < 4; j++) ct[tt][j] = 0.f;

#pragma unroll
        for (int c = 0; c < 4; c++) {
            float s00, c00, s01, c01, s10, c10, s11, c11;
            __sincosf(p0[c] * fr0, &s00, &c00);
            __sincosf(p0[c] * fr1, &s01, &c01);
            __sincosf(p1[c] * fr0, &s10, &c10);
            __sincosf(p1[c] * fr1, &s11, &c11);
            uint32_t asin_[4] = {f2tf32(s00), f2tf32(s10), f2tf32(s01), f2tf32(s11)};
            uint32_t acos_[4] = {f2tf32(c00), f2tf32(c10), f2tf32(c01), f2tf32(c11)};
            mma_tf32(ct[0], asin_, breg[0][2 * c]);
            mma_tf32(ct[1], asin_, breg[1][2 * c]);
            mma_tf32(ct[0], acos_, breg[0][2 * c + 1]);
            mma_tf32(ct[1], acos_, breg[1][2 * c + 1]);
        }

#pragma unroll
        for (int tt = 0; tt < 2; tt++) {
            int gc = 8 * tt + 2 * t3;
            float v0 = fmaxf(ct[tt][0] + bias[tt][0], 0.f) + 1e-6f;
            float v1 = fmaxf(ct[tt][1] + bias[tt][1], 0.f) + 1e-6f;
            float v2 = fmaxf(ct[tt][2] + bias[tt][0], 0.f) + 1e-6f;
            float v3 = fmaxf(ct[tt][3] + bias[tt][1], 0.f) + 1e-6f;
            Lpn[(size_t)gc * MM + m0p]       = __float2half_rn(v0);
            Lpn[(size_t)(gc + 1) * MM + m0p] = __float2half_rn(v1);
            Lpn[(size_t)gc * MM + m1p]       = __float2half_rn(v2);
            Lpn[(size_t)(gc + 1) * MM + m1p] = __float2half_rn(v3);
        }
    }
}

// ===========================================================================
// Prelude dispatcher: 1312 blocks (R12 mapping).
//   bid < 576: even -> proj(bid/2) [0..287], odd -> pos chunk bid/2 [0..287]
//   bid >= 576: pos chunk (bid - 288)        [288..1023]
// pos chunk id c: n = c >> 1, mh = c & 1.
// proj id p: p < 32 -> Q projection (grid 8x4); else p-32 -> K|V (grid 16x16).
// ===========================================================================
__global__ void __launch_bounds__(256, 2) prelude_kernel(
    const float* __restrict__ bbox, const float* __restrict__ ref_bbox,
    const float* __restrict__ roi_feat, const float* __restrict__ ref_feat,
    const float* __restrict__ Wg_w, const float* __restrict__ Wg_b,
    const float* __restrict__ Wq_w, const float* __restrict__ Wq_b,
    const float* __restrict__ Wk_w, const float* __restrict__ Wk_b,
    const float* __restrict__ Wv_w, const float* __restrict__ Wv_b,
    const float* __restrict__ u,
    float* __restrict__ Qd, __half* __restrict__ Kd, __half* __restrict__ VTd)
{
    const int bid = blockIdx.x;
    int proj = -1, posc = -1;
    if (bid < 576) {
        if ((bid & 1) == 0) proj = bid >> 1;
        else posc = bid >> 1;
    } else {
        posc = bid - 288;
    }

    if (posc >= 0) {
        pos_body(posc >> 1, posc & 1, bbox, ref_bbox, Wg_w, Wg_b);
        return;
    }

    const float *A, *B, *cb0, *cb1 = nullptr;
    void* C;
    int i0, j0, mode;
    float alpha;
    if (proj < 32) {                 // Q projection: grid 8 x 4 over (FF, NN)
        int bx = proj & 7, by = proj >> 3;
        A = roi_feat; B = Wq_w; C = Qd; cb0 = Wq_b; cb1 = u;
        i0 = by * 128; j0 = bx * 128; mode = 0; alpha = 0.125f;
    } else {                         // K|V projection: grid 16 x 16 over (2FF, MM)
        int p = proj - 32;
        int bx = p & 15, by = p >> 4;
        A = ref_feat;
        i0 = by * 128; j0 = bx * 128; alpha = 1.f;
        if (j0 < FF) { B = Wk_w; C = Kd; cb0 = Wk_b; mode = 1; }
        else         { B = Wv_w; C = VTd; cb0 = Wv_b; mode = 2; j0 -= FF; }
    }
    proj_body(A, FF, B, FF, C, FF, FF, alpha, cb0, cb1, i0, j0, mode);
}

// ===========================================================================
// Flash attention (fp16 mma): block = (n-tile 64, head g, split). 2 blocks/SM.
// Q is pre-scaled by 0.125 at projection time (exact power of two).
// ===========================================================================
#define KB_U32 (128 * 36)
#define VB_U32 (64 * 68)
#define PP_U32 68
#define FLASH_SMEM_BYTES ((2 * KB_U32 + 2 * VB_U32 + 64 * PP_U32) * 4)
#define FL_TILES ((MM / SPLIT) / 128)   // 8

__global__ void __launch_bounds__(256, 2) flash_kernel()
{
    extern __shared__ uint32_t smem[];
    uint32_t* sK = smem;                           // [2][128][36] u32
    uint32_t* sV = smem + 2 * KB_U32;              // [2][64][68] u32
    uint32_t* sP = smem + 2 * KB_U32 + 2 * VB_U32; // [64][68] u32

    __shared__ float sRmax[2][64];
    __shared__ float sRsum[2][64];

    const int t = threadIdx.x;
    const int w = t >> 5, lane = t & 31;
    const int g5 = lane >> 2, t3 = lane & 3;
    const int wr = w & 3, wc = w >> 2;
    const int n0 = blockIdx.x * 64;
    const int g = blockIdx.y;
    const int sp = blockIdx.z;
    const int m_base = sp * (MM / SPLIT);

    const uint32_t kb = (uint32_t)__cvta_generic_to_shared(sK);
    const uint32_t vb = (uint32_t)__cvta_generic_to_shared(sV);

    // ---- Q tile (64x64 fp32, pre-scaled) -> staging -> fp16 fragments ---
    {
        float* sPf = (float*)sP;                 // pitch 68 floats
#pragma unroll
        for (int i = 0; i < 4; i++) {
            int f = t + i * 256;
            int row = f >> 4, c4 = (f & 15) << 2;
            *(float4*)&sPf[row * 68 + c4] =
                *(const float4*)(g_Q + (size_t)(n0 + row) * FF + g * 64 + c4);
        }
    }
    __syncthreads();
    const int rl0 = 16 * wr + g5, rl1 = rl0 + 8;
    uint32_t qf[4][4];
    {
        const float* sPf = (const float*)sP;
        int r = 16 * wr + g5;
#pragma unroll
        for (int s = 0; s < 4; s++) {
            float2 x0 = *(const float2*)&sPf[r * 68 + 16 * s + 2 * t3];
            float2 x1 = *(const float2*)&sPf[(r + 8) * 68 + 16 * s + 2 * t3];
            float2 x2 = *(const float2*)&sPf[r * 68 + 16 * s + 2 * t3 + 8];
            float2 x3 = *(const float2*)&sPf[(r + 8) * 68 + 16 * s + 2 * t3 + 8];
            qf[s][0] = packh2(x0.x, x0.y);
            qf[s][1] = packh2(x1.x, x1.y);
            qf[s][2] = packh2(x2.x, x2.y);
            qf[s][3] = packh2(x3.x, x3.y);
        }
    }

    // ---- K / V^T tile loaders (cp.async, fp16) --------------------------
    auto load_kv = [&](int buf, int m0) {
#pragma unroll
        for (int i = 0; i < 4; i++) {            // K: 128 rows x 128B
            int f = t + i * 256;
            int row = f >> 3, h8 = (f & 7) * 8;
            cp16(kb + (uint32_t)((buf * KB_U32 + row * 36) * 4 + h8 * 2),
                 g_K + (size_t)(m0 + row) * FF + g * 64 + h8);
        }
#pragma unroll
        for (int i = 0; i < 4; i++) {            // VT: 64 rows x 256B
            int f = t + i * 256;
            int row = f >> 4, h8 = (f & 15) * 8;
            cp16(vb + (uint32_t)((buf * VB_U32 + row * 68) * 4 + h8 * 2),
                 g_VT + (size_t)(g * 64 + row) * MM + m0 + h8);
        }
        asm volatile("cp.async.commit_group;");
    };

    load_kv(0, m_base);
    __syncthreads();   // Q staging in sP consumed before first P write

    float rmax0 = -1e30f, rmax1 = -1e30f, rsum0 = 0.f, rsum1 = 0.f;
    float oc[4][4];
#pragma unroll
    for (int a = 0; a < 4; a++)
#pragma unroll
        for (int b = 0; b < 4; b++) oc[a][b] = 0.f;

    for (int mt = 0; mt < FL_TILES; mt++) {
        if (mt + 1 < FL_TILES) {
            load_kv((mt + 1) & 1, m_base + (mt + 1) * 128);
            asm volatile("cp.async.wait_group 1;");
        } else {
            asm volatile("cp.async.wait_group 0;");
        }
        __syncthreads();

        const uint32_t* Ku = sK + (mt & 1) * KB_U32;
        const uint32_t* Vu = sV + (mt & 1) * VB_U32;

        // pos weights (fp16, multiplicative)
        __half2 lp0[8], lp1[8];
        {
            size_t base0 = ((size_t)(n0 + rl0) * GG + g) * MM
                         + m_base + mt * 128 + 64 * wc + 2 * t3;
            size_t base1 = base0 + (size_t)8 * GG * MM;
#pragma unroll
            for (int tn = 0; tn < 8; tn++) {
                lp0[tn] = *(const __half2*)(g_L + base0 + 8 * tn);
                lp1[tn] = *(const __half2*)(g_L + base1 + 8 * tn);
            }
        }

        // ---- S = Q K^T (Q pre-scaled) ------------------------------------
        float sc[8][4];
#pragma unroll
        for (int a = 0; a < 8; a++)
#pragma unroll
            for (int b = 0; b < 4; b++) sc[a][b] = 0.f;
#pragma unroll
        for (int s = 0; s < 4; s++)
#pragma unroll
            for (int tn = 0; tn < 8; tn++) {
                uint32_t bfr[2];
                int mr = 64 * wc + 8 * tn + g5;
                bfr[0] = Ku[mr * 36 + 8 * s + t3];
                bfr[1] = Ku[mr * 36 + 8 * s + 4 + t3];
                mma_f16(sc[tn], qf[s], bfr);
            }

        // content-score max
        float pm0 = -1e30f, pm1 = -1e30f;
#pragma unroll
        for (int tn = 0; tn < 8; tn++) {
            pm0 = fmaxf(pm0, fmaxf(sc[tn][0], sc[tn][1]));
            pm1 = fmaxf(pm1, fmaxf(sc[tn][2], sc[tn][3]));
        }
        pm0 = fmaxf(pm0, __shfl_xor_sync(~0u, pm0, 1));
        pm0 = fmaxf(pm0, __shfl_xor_sync(~0u, pm0, 2));
        pm1 = fmaxf(pm1, __shfl_xor_sync(~0u, pm1, 1));
        pm1 = fmaxf(pm1, __shfl_xor_sync(~0u, pm1, 2));
        if (t3 == 0) { sRmax[wc][rl0] = pm0; sRmax[wc][rl1] = pm1; }
        __syncthreads();

        float nm0 = fmaxf(rmax0, fmaxf(sRmax[0][rl0], sRmax[1][rl0]));
        float nm1 = fmaxf(rmax1, fmaxf(sRmax[0][rl1], sRmax[1][rl1]));
        float fs0 = __expf(rmax0 - nm0);
        float fs1 = __expf(rmax1 - nm1);
        rmax0 = nm0; rmax1 = nm1;
#pragma unroll
        for (int td = 0; td < 4; td++) {
            oc[td][0] *= fs0; oc[td][1] *= fs0;
            oc[td][2] *= fs1; oc[td][3] *= fs1;
        }

        // ---- P = w * exp(a - max), fp16 into sP -------------------------
        float ps0 = 0.f, ps1 = 0.f;
#pragma unroll
        for (int tn = 0; tn < 8; tn++) {
            float2 w0 = __half22float2(lp0[tn]);
            float2 w1 = __half22float2(lp1[tn]);
            float p0 = w0.x * __expf(sc[tn][0] - nm0);
            float p1 = w0.y * __expf(sc[tn][1] - nm0);
            float p2 = w1.x * __expf(sc[tn][2] - nm1);
            float p3 = w1.y * __expf(sc[tn][3] - nm1);
            ps0 += p0 + p1; ps1 += p2 + p3;
            int colq = 32 * wc + 4 * tn + t3;
            sP[rl0 * PP_U32 + colq] = packh2(p0, p1);
            sP[rl1 * PP_U32 + colq] = packh2(p2, p3);
        }
        ps0 += __shfl_xor_sync(~0u, ps0, 1);
        ps0 += __shfl_xor_sync(~0u, ps0, 2);
        ps1 += __shfl_xor_sync(~0u, ps1, 1);
        ps1 += __shfl_xor_sync(~0u, ps1, 2);
        if (t3 == 0) { sRsum[wc][rl0] = ps0; sRsum[wc][rl1] = ps1; }
        __syncthreads();

        rsum0 = rsum0 * fs0 + sRsum[0][rl0] + sRsum[1][rl0];
        rsum1 = rsum1 * fs1 + sRsum[0][rl1] + sRsum[1][rl1];

        // ---- O += P V ----------------------------------------------------
#pragma unroll
        for (int s = 0; s < 8; s++) {
            uint32_t af[4];
            af[0] = sP[rl0 * PP_U32 + 8 * s + t3];
            af[1] = sP[rl1 * PP_U32 + 8 * s + t3];
            af[2] = sP[rl0 * PP_U32 + 8 * s + 4 + t3];
            af[3] = sP[rl1 * PP_U32 + 8 * s + 4 + t3];
#pragma unroll
            for (int td = 0; td < 4; td++) {
                uint32_t bfr[2];
                int dcol = 32 * wc + 8 * td + g5;
                bfr[0] = Vu[dcol * 68 + 8 * s + t3];
                bfr[1] = Vu[dcol * 68 + 8 * s + 4 + t3];
                mma_f16(oc[td], af, bfr);
            }
        }
        __syncthreads();
    }

    // ---- partial epilogue -----------------------------------------------
    float* O0 = &g_O[sp][n0 + rl0][g * 64];
    float* O1 = O0 + (size_t)8 * FF;
#pragma unroll
    for (int td = 0; td < 4; td++) {
        int c = 32 * wc + 8 * td + 2 * t3;
        *(float2*)(O0 + c) = make_float2(oc[td][0], oc[td][1]);
        *(float2*)(O1 + c) = make_float2(oc[td][2], oc[td][3]);
    }
    if (t3 == 0 && wc == 0) {
        g_Mx[sp][n0 + rl0][g] = rmax0;     g_Sm[sp][n0 + rl0][g] = rsum0;
        g_Mx[sp][n0 + rl1][g] = rmax1;     g_Sm[sp][n0 + rl1][g] = rsum1;
    }
}

// ===========================================================================
// Combine the SPLIT partial outputs.
// ===========================================================================
__global__ void __launch_bounds__(256) combine_kernel(float* __restrict__ out)
{
    int idx = blockIdx.x * 256 + threadIdx.x;     // one float2 per thread
    int n = idx / (FF / 2);
    int c = (idx - n * (FF / 2)) * 2;
    int g = c >> 6;
    float m0 = g_Mx[0][n][g], m1 = g_Mx[1][n][g];
    float Mx = fmaxf(m0, m1);
    float w0 = __expf(m0 - Mx), w1 = __expf(m1 - Mx);
    float inv = 1.f / (g_Sm[0][n][g] * w0 + g_Sm[1][n][g] * w1);
    float2 a = *(const float2*)&g_O[0][n][c];
    float2 b = *(const float2*)&g_O[1][n][c];
    *(float2*)&out[(size_t)n * FF + c] =
        make_float2((a.x * w0 + b.x * w1) * inv, (a.y * w0 + b.y * w1) * inv);
}

// ===========================================================================
extern "C" void kernel_launch(void* const* d_in, const int* in_sizes, int n_in,
                              void* d_out, int out_size)
{
    (void)in_sizes; (void)n_in; (void)out_size;
    const float* bbox     = (const float*)d_in[0];
    const float* ref_bbox = (const float*)d_in[1];
    const float* roi_feat = (const float*)d_in[2];
    const float* ref_feat = (const float*)d_in[3];
    const float* Wg_w     = (const float*)d_in[4];
    const float* Wg_b     = (const float*)d_in[5];
    const float* Wq_w     = (const float*)d_in[6];
    const float* Wq_b     = (const float*)d_in[7];
    const float* Wk_w     = (const float*)d_in[8];
    const float* Wk_b     = (const float*)d_in[9];
    const float* Wv_w     = (const float*)d_in[10];  // [16,64,1024] == [1024,1024]
    const float* Wv_b     = (const float*)d_in[11];
    const float* u        = (const float*)d_in[12];  // [16,1,64] == [1024]
    float* out = (float*)d_out;

    float* Qd; __half *Kd, *VTd;
    cudaGetSymbolAddress((void**)&Qd, g_Q);
    cudaGetSymbolAddress((void**)&Kd, g_K);
    cudaGetSymbolAddress((void**)&VTd, g_VT);

    cudaFuncSetAttribute(flash_kernel,
                         cudaFuncAttributeMaxDynamicSharedMemorySize,
                         FLASH_SMEM_BYTES);

    dim3 thr(256);

    // fused prelude: pos weights (half-m quanta) + Q proj + K|V proj
    prelude_kernel<<<1312, thr>>>(bbox, ref_bbox, roi_feat, ref_feat,
                                  Wg_w, Wg_b, Wq_w, Wq_b, Wk_w, Wk_b,
                                  Wv_w, Wv_b, u, Qd, Kd, VTd);
    // fused attention (fp16 mma, split-K over m) + combine
    flash_kernel<<<dim3(NN / 64, GG, SPLIT), thr, FLASH_SMEM_BYTES>>>();
    combine_kernel<<<NN * FF / 2 / 256, thr>>>(out);
}

// round 14
// speedup vs baseline: 2.1500x; 1.1417x over previous
#include <cuda_runtime.h>
#include <cuda_fp16.h>
#include <cstdint>
#include <cstddef>

#define NN 512
#define MM 2048
#define FF 1024
#define GG 16
#define DD 64
#define SPLIT 2

// -------- scratch ----------------------------------------------------------
__device__ float  g_Q[NN * FF];                 // Q' = 0.125*(roi@Wq^T + b + u) (fp32)
__device__ __half g_K[MM * FF];                 // K  (fp16, [m][d])
__device__ __half g_VT[FF * MM];                // V^T (fp16, [d][m])
__device__ __half g_L[(size_t)NN * GG * MM];    // w = relu(Wg.emb+b)+1e-6 (fp16)
__device__ float  g_O[SPLIT][NN][FF];           // unnormalized partial outputs
__device__ float  g_Mx[SPLIT][NN][GG];          // partial content-score max
__device__ float  g_Sm[SPLIT][NN][GG];          // partial row sum

__constant__ float c_freq[8] = {
    100.0f,        42.16965034f, 17.78279410f, 7.498942093f,
    3.162277660f,  1.333521432f, 0.5623413252f, 0.2371373706f};

__device__ __forceinline__ uint32_t f2tf32(float f) {
    uint32_t u;
    asm("cvt.rna.tf32.f32 %0, %1;" : "=r"(u) : "f"(f));
    return u;
}

__device__ __forceinline__ uint32_t packh2(float lo, float hi) {
    uint32_t r;
    asm("cvt.rn.f16x2.f32 %0, %1, %2;" : "=r"(r) : "f"(hi), "f"(lo));
    return r;
}

__device__ __forceinline__ void mma_tf32(float* c, const uint32_t* a, const uint32_t* b) {
    asm volatile(
        "mma.sync.aligned.m16n8k8.row.col.f32.tf32.tf32.f32 "
        "{%0,%1,%2,%3}, {%4,%5,%6,%7}, {%8,%9}, {%0,%1,%2,%3};"
        : "+f"(c[0]), "+f"(c[1]), "+f"(c[2]), "+f"(c[3])
        : "r"(a[0]), "r"(a[1]), "r"(a[2]), "r"(a[3]), "r"(b[0]), "r"(b[1]));
}

__device__ __forceinline__ void mma_f16(float* c, const uint32_t* a, const uint32_t* b) {
    asm volatile(
        "mma.sync.aligned.m16n8k16.row.col.f32.f16.f16.f32 "
        "{%0,%1,%2,%3}, {%4,%5,%6,%7}, {%8,%9}, {%0,%1,%2,%3};"
        : "+f"(c[0]), "+f"(c[1]), "+f"(c[2]), "+f"(c[3])
        : "r"(a[0]), "r"(a[1]), "r"(a[2]), "r"(a[3]), "r"(b[0]), "r"(b[1]));
}

__device__ __forceinline__ void ldsm_x4(uint32_t* r, uint32_t addr) {
    asm volatile("ldmatrix.sync.aligned.m8n8.x4.shared.b16 {%0,%1,%2,%3}, [%4];"
        : "=r"(r[0]), "=r"(r[1]), "=r"(r[2]), "=r"(r[3]) : "r"(addr));
}

__device__ __forceinline__ void ldsm_x2(uint32_t* r, uint32_t addr) {
    asm volatile("ldmatrix.sync.aligned.m8n8.x2.shared.b16 {%0,%1}, [%2];"
        : "=r"(r[0]), "=r"(r[1]) : "r"(addr));
}

__device__ __forceinline__ void cp16(uint32_t d, const void* s) {
    asm volatile("cp.async.cg.shared.global [%0], [%1], 16;" :: "r"(d), "l"(s));
}

// ===========================================================================
// Projection GEMM body, fp16 datapath (mma.m16n8k16, 128x128 tile, BK=16,
// double buffered). fp32->f16x2 pack at smem store; fp32 accumulate.
// Fragments via ldmatrix (8 LDSM/warp/kt instead of 24 LDS.32).
// smem pitch 12 u32 (48B) per 16-half row: ldmatrix row starts 48*i mod 128
// cover all 32 banks -> conflict-free.
// mode: 0 = fp32 [i][j]; 1 = fp16 [i][j]; 2 = fp16 T [j][i] (ld MM).
// Epilogue: v = (acc + bias) * alpha  (alpha = exact power of two).
// ===========================================================================
__device__ __noinline__ void proj_body(
    const float* __restrict__ A, int lda,
    const float* __restrict__ Bb, int ldb,
    void* __restrict__ Cb, int ldc,
    int Kdim, float alpha,
    const float* __restrict__ cb0, const float* __restrict__ cb1,
    int i0, int j0, int mode)
{
    __shared__ uint32_t sA[2][128 * 12];
    __shared__ uint32_t sB[2][128 * 12];

    const int t = threadIdx.x;
    const int w = t >> 5, lane = t & 31;
    const int g = lane >> 2, tig = lane & 3;
    const int wm = w & 1, wn = w >> 1;          // 2 x 4 warp grid

    // loader precompute: 2 float4 per thread per tile for each matrix
    const float* aPtr[2]; int aIdx[2];
    const float* bPtr[2]; int bIdx[2];
#pragma unroll
    for (int ia = 0; ia < 2; ia++) {
        int fidx = ia * 256 + t;
        int row = fidx >> 2, kq = fidx & 3;
        aPtr[ia] = A + (size_t)(i0 + row) * lda + kq * 4;
        bPtr[ia] = Bb + (size_t)(j0 + row) * ldb + kq * 4;
        aIdx[ia] = row * 12 + 2 * kq;
        bIdx[ia] = row * 12 + 2 * kq;
    }

    // ldmatrix per-lane base addresses (buffer 0; +6144 bytes for buffer 1)
    // A x4 tiles: t0 rows r+0..7 k0-7 | t1 rows r+8..15 k0-7 | t2/t3 same +16B
    const uint32_t aSmem = (uint32_t)__cvta_generic_to_shared(&sA[0][0]);
    const uint32_t bSmem = (uint32_t)__cvta_generic_to_shared(&sB[0][0]);
    const uint32_t aLane = aSmem
        + (uint32_t)((wm * 64 + ((lane >> 3) & 1) * 8 + (lane & 7)) * 48
                     + ((lane & 16) ? 16 : 0));
    // B x2 tiles: t0 rows n+0..7 k0-7 | t1 rows n+0..7 k8-15 (+16B)
    const uint32_t bLane = bSmem
        + (uint32_t)((wn * 32 + (lane & 7)) * 48 + ((lane & 8) ? 16 : 0));

    float acc[4][4][4];
#pragma unroll
    for (int a = 0; a < 4; a++)
#pragma unroll
        for (int b = 0; b < 4; b++)
#pragma unroll
            for (int c = 0; c < 4; c++) acc[a][b][c] = 0.f;

    const int KT = Kdim / 16;
    float4 ra[2], rb[2];

    // prologue: tile 0
#pragma unroll
    for (int ia = 0; ia < 2; ia++) { ra[ia] = *(const float4*)(aPtr[ia]);
                                     rb[ia] = *(const float4*)(bPtr[ia]); }
#pragma unroll
    for (int ia = 0; ia < 2; ia++) {
        *(uint2*)&sA[0][aIdx[ia]] = make_uint2(packh2(ra[ia].x, ra[ia].y),
                                               packh2(ra[ia].z, ra[ia].w));
        *(uint2*)&sB[0][bIdx[ia]] = make_uint2(packh2(rb[ia].x, rb[ia].y),
                                               packh2(rb[ia].z, rb[ia].w));
    }
    __syncthreads();

    for (int kt = 0; kt < KT; kt++) {
        const int cur = kt & 1;
        if (kt + 1 < KT) {
#pragma unroll
            for (int ia = 0; ia < 2; ia++) {
                ra[ia] = *(const float4*)(aPtr[ia] + (kt + 1) * 16);
                rb[ia] = *(const float4*)(bPtr[ia] + (kt + 1) * 16);
            }
        }
        const uint32_t bufOff = (uint32_t)(cur * 6144);
        uint32_t af[4][4], bf[4][2];
#pragma unroll
        for (int tn = 0; tn < 4; tn++)
            ldsm_x2(bf[tn], bLane + bufOff + tn * 384);    // 8 rows * 48B
#pragma unroll
        for (int tm = 0; tm < 4; tm++)
            ldsm_x4(af[tm], aLane + bufOff + tm * 768);    // 16 rows * 48B
#pragma unroll
        for (int tm = 0; tm < 4; tm++)
#pragma unroll
            for (int tn = 0; tn < 4; tn++)
                mma_f16(acc[tm][tn], af[tm], bf[tn]);

        if (kt + 1 < KT) {
            const int nxt = cur ^ 1;
#pragma unroll
            for (int ia = 0; ia < 2; ia++) {
                *(uint2*)&sA[nxt][aIdx[ia]] = make_uint2(packh2(ra[ia].x, ra[ia].y),
                                                         packh2(ra[ia].z, ra[ia].w));
                *(uint2*)&sB[nxt][bIdx[ia]] = make_uint2(packh2(rb[ia].x, rb[ia].y),
                                                         packh2(rb[ia].z, rb[ia].w));
            }
        }
        __syncthreads();
    }

    // ---- epilogue: v = (acc + bias) * alpha ------------------------------
#pragma unroll
    for (int tm = 0; tm < 4; tm++) {
        int r = i0 + wm * 64 + tm * 16 + g;
#pragma unroll
        for (int tn = 0; tn < 4; tn++) {
            int c = j0 + wn * 32 + tn * 8 + tig * 2;
            float b0 = 0.f, b1 = 0.f;
            if (cb0) { b0 += cb0[c]; b1 += cb0[c + 1]; }
            if (cb1) { b0 += cb1[c]; b1 += cb1[c + 1]; }
            float v0 = (acc[tm][tn][0] + b0) * alpha;
            float v1 = (acc[tm][tn][1] + b1) * alpha;
            float v2 = (acc[tm][tn][2] + b0) * alpha;
            float v3 = (acc[tm][tn][3] + b1) * alpha;
            if (mode == 0) {
                float* Cf = (float*)Cb;
                *(float2*)(Cf + (size_t)r * ldc + c) = make_float2(v0, v1);
                *(float2*)(Cf + (size_t)(r + 8) * ldc + c) = make_float2(v2, v3);
            } else if (mode == 1) {
                __half* Ch = (__half*)Cb;
                *(uint32_t*)(Ch + (size_t)r * ldc + c) = packh2(v0, v1);
                *(uint32_t*)(Ch + (size_t)(r + 8) * ldc + c) = packh2(v2, v3);
            } else {
                __half* Ch = (__half*)Cb;        // [j][i], stride MM
                Ch[(size_t)c * MM + r]           = __float2half_rn(v0);
                Ch[(size_t)(c + 1) * MM + r]     = __float2half_rn(v1);
                Ch[(size_t)c * MM + r + 8]       = __float2half_rn(v2);
                Ch[(size_t)(c + 1) * MM + r + 8] = __float2half_rn(v3);
            }
        }
    }
}

// ===========================================================================
// pos body: w[n][g][m] = relu(emb(n,m,:)·Wg[g,:]+b) + 1e-6, fp16 out.
// One block covers HALF the m-range (mh in {0,1}) for one n.
// ===========================================================================
__device__ __noinline__ void pos_body(
    int n, int mh,
    const float* __restrict__ bbox, const float* __restrict__ ref_bbox,
    const float* __restrict__ Wg_w, const float* __restrict__ Wg_b)
{
    const int t = threadIdx.x;
    const int w = t >> 5, lane = t & 31;
    const int g5 = lane >> 2, t3 = lane & 3;

    float x0 = bbox[n * 4 + 0], y0 = bbox[n * 4 + 1];
    float x1 = bbox[n * 4 + 2], y1 = bbox[n * 4 + 3];
    float bw = x1 - x0 + 1.f, bh = y1 - y0 + 1.f;
    float cx = 0.5f * (x0 + x1), cy = 0.5f * (y0 + y1);
    float iw = 1.f / bw, ih = 1.f / bh;
    float lw = __logf(bw), lh = __logf(bh);

    uint32_t breg[2][8][2];
#pragma unroll
    for (int tt = 0; tt < 2; tt++)
#pragma unroll
        for (int s = 0; s < 8; s++) {
            breg[tt][s][0] = f2tf32(Wg_w[(8 * tt + g5) * 64 + 8 * s + t3]);
            breg[tt][s][1] = f2tf32(Wg_w[(8 * tt + g5) * 64 + 8 * s + 4 + t3]);
        }
    float bias[2][2];
#pragma unroll
    for (int tt = 0; tt < 2; tt++) {
        bias[tt][0] = Wg_b[8 * tt + 2 * t3];
        bias[tt][1] = Wg_b[8 * tt + 2 * t3 + 1];
    }
    const float fr0 = c_freq[t3], fr1 = c_freq[t3 + 4];

    __half* Lpn = g_L + (size_t)n * GG * MM;

    for (int it = 0; it < 8; it++) {
        const int mbase = (mh * 64 + it * 8 + w) * 16;
        const int m0p = mbase + g5, m1p = m0p + 8;

        float4 rb0 = *(const float4*)(ref_bbox + (size_t)m0p * 4);
        float4 rb1 = *(const float4*)(ref_bbox + (size_t)m1p * 4);
        float p0[4], p1[4];
        {
            float wr = rb0.z - rb0.x + 1.f, hr = rb0.w - rb0.y + 1.f;
            float cxr = 0.5f * (rb0.x + rb0.z), cyr = 0.5f * (rb0.y + rb0.w);
            p0[0] = __logf(fabsf((cx - cxr) * iw) + 1e-3f);
            p0[1] = __logf(fabsf((cy - cyr) * ih) + 1e-3f);
            p0[2] = lw - __logf(wr);
            p0[3] = lh - __logf(hr);
        }
        {
            float wr = rb1.z - rb1.x + 1.f, hr = rb1.w - rb1.y + 1.f;
            float cxr = 0.5f * (rb1.x + rb1.z), cyr = 0.5f * (rb1.y + rb1.w);
            p1[0] = __logf(fabsf((cx - cxr) * iw) + 1e-3f);
            p1[1] = __logf(fabsf((cy - cyr) * ih) + 1e-3f);
            p1[2] = lw - __logf(wr);
            p1[3] = lh - __logf(hr);
        }

        float ct[2][4];
#pragma unroll
        for (int tt = 0; tt < 2; tt++)
#pragma unroll
            for (int j = 0; j < 4; j++) ct[tt][j] = 0.f;

#pragma unroll
        for (int c = 0; c < 4; c++) {
            float s00, c00, s01, c01, s10, c10, s11, c11;
            __sincosf(p0[c] * fr0, &s00, &c00);
            __sincosf(p0[c] * fr1, &s01, &c01);
            __sincosf(p1[c] * fr0, &s10, &c10);
            __sincosf(p1[c] * fr1, &s11, &c11);
            uint32_t asin_[4] = {f2tf32(s00), f2tf32(s10), f2tf32(s01), f2tf32(s11)};
            uint32_t acos_[4] = {f2tf32(c00), f2tf32(c10), f2tf32(c01), f2tf32(c11)};
            mma_tf32(ct[0], asin_, breg[0][2 * c]);
            mma_tf32(ct[1], asin_, breg[1][2 * c]);
            mma_tf32(ct[0], acos_, breg[0][2 * c + 1]);
            mma_tf32(ct[1], acos_, breg[1][2 * c + 1]);
        }

#pragma unroll
        for (int tt = 0; tt < 2; tt++) {
            int gc = 8 * tt + 2 * t3;
            float v0 = fmaxf(ct[tt][0] + bias[tt][0], 0.f) + 1e-6f;
            float v1 = fmaxf(ct[tt][1] + bias[tt][1], 0.f) + 1e-6f;
            float v2 = fmaxf(ct[tt][2] + bias[tt][0], 0.f) + 1e-6f;
            float v3 = fmaxf(ct[tt][3] + bias[tt][1], 0.f) + 1e-6f;
            Lpn[(size_t)gc * MM + m0p]       = __float2half_rn(v0);
            Lpn[(size_t)(gc + 1) * MM + m0p] = __float2half_rn(v1);
            Lpn[(size_t)gc * MM + m1p]       = __float2half_rn(v2);
            Lpn[(size_t)(gc + 1) * MM + m1p] = __float2half_rn(v3);
        }
    }
}

// ===========================================================================
// Prelude dispatcher: 1312 blocks (R12 mapping).
//   bid < 576: even -> proj(bid/2) [0..287], odd -> pos chunk bid/2 [0..287]
//   bid >= 576: pos chunk (bid - 288)        [288..1023]
// pos chunk id c: n = c >> 1, mh = c & 1.
// proj id p: p < 32 -> Q projection (grid 8x4); else p-32 -> K|V (grid 16x16).
// ===========================================================================
__global__ void __launch_bounds__(256, 2) prelude_kernel(
    const float* __restrict__ bbox, const float* __restrict__ ref_bbox,
    const float* __restrict__ roi_feat, const float* __restrict__ ref_feat,
    const float* __restrict__ Wg_w, const float* __restrict__ Wg_b,
    const float* __restrict__ Wq_w, const float* __restrict__ Wq_b,
    const float* __restrict__ Wk_w, const float* __restrict__ Wk_b,
    const float* __restrict__ Wv_w, const float* __restrict__ Wv_b,
    const float* __restrict__ u,
    float* __restrict__ Qd, __half* __restrict__ Kd, __half* __restrict__ VTd)
{
    const int bid = blockIdx.x;
    int proj = -1, posc = -1;
    if (bid < 576) {
        if ((bid & 1) == 0) proj = bid >> 1;
        else posc = bid >> 1;
    } else {
        posc = bid - 288;
    }

    if (posc >= 0) {
        pos_body(posc >> 1, posc & 1, bbox, ref_bbox, Wg_w, Wg_b);
        return;
    }

    const float *A, *B, *cb0, *cb1 = nullptr;
    void* C;
    int i0, j0, mode;
    float alpha;
    if (proj < 32) {                 // Q projection: grid 8 x 4 over (FF, NN)
        int bx = proj & 7, by = proj >> 3;
        A = roi_feat; B = Wq_w; C = Qd; cb0 = Wq_b; cb1 = u;
        i0 = by * 128; j0 = bx * 128; mode = 0; alpha = 0.125f;
    } else {                         // K|V projection: grid 16 x 16 over (2FF, MM)
        int p = proj - 32;
        int bx = p & 15, by = p >> 4;
        A = ref_feat;
        i0 = by * 128; j0 = bx * 128; alpha = 1.f;
        if (j0 < FF) { B = Wk_w; C = Kd; cb0 = Wk_b; mode = 1; }
        else         { B = Wv_w; C = VTd; cb0 = Wv_b; mode = 2; j0 -= FF; }
    }
    proj_body(A, FF, B, FF, C, FF, FF, alpha, cb0, cb1, i0, j0, mode);
}

// ===========================================================================
// Flash attention (fp16 mma): block = (n-tile 64, head g, split). 2 blocks/SM.
// Q is pre-scaled by 0.125 at projection time (exact power of two).
// ===========================================================================
#define KB_U32 (128 * 36)
#define VB_U32 (64 * 68)
#define PP_U32 68
#define FLASH_SMEM_BYTES ((2 * KB_U32 + 2 * VB_U32 + 64 * PP_U32) * 4)
#define FL_TILES ((MM / SPLIT) / 128)   // 8

__global__ void __launch_bounds__(256, 2) flash_kernel()
{
    extern __shared__ uint32_t smem[];
    uint32_t* sK = smem;                           // [2][128][36] u32
    uint32_t* sV = smem + 2 * KB_U32;              // [2][64][68] u32
    uint32_t* sP = smem + 2 * KB_U32 + 2 * VB_U32; // [64][68] u32

    __shared__ float sRmax[2][64];
    __shared__ float sRsum[2][64];

    const int t = threadIdx.x;
    const int w = t >> 5, lane = t & 31;
    const int g5 = lane >> 2, t3 = lane & 3;
    const int wr = w & 3, wc = w >> 2;
    const int n0 = blockIdx.x * 64;
    const int g = blockIdx.y;
    const int sp = blockIdx.z;
    const int m_base = sp * (MM / SPLIT);

    const uint32_t kb = (uint32_t)__cvta_generic_to_shared(sK);
    const uint32_t vb = (uint32_t)__cvta_generic_to_shared(sV);

    // ---- Q tile (64x64 fp32, pre-scaled) -> staging -> fp16 fragments ---
    {
        float* sPf = (float*)sP;                 // pitch 68 floats
#pragma unroll
        for (int i = 0; i < 4; i++) {
            int f = t + i * 256;
            int row = f >> 4, c4 = (f & 15) << 2;
            *(float4*)&sPf[row * 68 + c4] =
                *(const float4*)(g_Q + (size_t)(n0 + row) * FF + g * 64 + c4);
        }
    }
    __syncthreads();
    const int rl0 = 16 * wr + g5, rl1 = rl0 + 8;
    uint32_t qf[4][4];
    {
        const float* sPf = (const float*)sP;
        int r = 16 * wr + g5;
#pragma unroll
        for (int s = 0; s < 4; s++) {
            float2 x0 = *(const float2*)&sPf[r * 68 + 16 * s + 2 * t3];
            float2 x1 = *(const float2*)&sPf[(r + 8) * 68 + 16 * s + 2 * t3];
            float2 x2 = *(const float2*)&sPf[r * 68 + 16 * s + 2 * t3 + 8];
            float2 x3 = *(const float2*)&sPf[(r + 8) * 68 + 16 * s + 2 * t3 + 8];
            qf[s][0] = packh2(x0.x, x0.y);
            qf[s][1] = packh2(x1.x, x1.y);
            qf[s][2] = packh2(x2.x, x2.y);
            qf[s][3] = packh2(x3.x, x3.y);
        }
    }

    // ---- K / V^T tile loaders (cp.async, fp16) --------------------------
    auto load_kv = [&](int buf, int m0) {
#pragma unroll
        for (int i = 0; i < 4; i++) {            // K: 128 rows x 128B
            int f = t + i * 256;
            int row = f >> 3, h8 = (f & 7) * 8;
            cp16(kb + (uint32_t)((buf * KB_U32 + row * 36) * 4 + h8 * 2),
                 g_K + (size_t)(m0 + row) * FF + g * 64 + h8);
        }
#pragma unroll
        for (int i = 0; i < 4; i++) {            // VT: 64 rows x 256B
            int f = t + i * 256;
            int row = f >> 4, h8 = (f & 15) * 8;
            cp16(vb + (uint32_t)((buf * VB_U32 + row * 68) * 4 + h8 * 2),
                 g_VT + (size_t)(g * 64 + row) * MM + m0 + h8);
        }
        asm volatile("cp.async.commit_group;");
    };

    load_kv(0, m_base);
    __syncthreads();   // Q staging in sP consumed before first P write

    float rmax0 = -1e30f, rmax1 = -1e30f, rsum0 = 0.f, rsum1 = 0.f;
    float oc[4][4];
#pragma unroll
    for (int a = 0; a < 4; a++)
#pragma unroll
        for (int b = 0; b < 4; b++) oc[a][b] = 0.f;

    for (int mt = 0; mt < FL_TILES; mt++) {
        if (mt + 1 < FL_TILES) {
            load_kv((mt + 1) & 1, m_base + (mt + 1) * 128);
            asm volatile("cp.async.wait_group 1;");
        } else {
            asm volatile("cp.async.wait_group 0;");
        }
        __syncthreads();

        const uint32_t* Ku = sK + (mt & 1) * KB_U32;
        const uint32_t* Vu = sV + (mt & 1) * VB_U32;

        // pos weights (fp16, multiplicative)
        __half2 lp0[8], lp1[8];
        {
            size_t base0 = ((size_t)(n0 + rl0) * GG + g) * MM
                         + m_base + mt * 128 + 64 * wc + 2 * t3;
            size_t base1 = base0 + (size_t)8 * GG * MM;
#pragma unroll
            for (int tn = 0; tn < 8; tn++) {
                lp0[tn] = *(const __half2*)(g_L + base0 + 8 * tn);
                lp1[tn] = *(const __half2*)(g_L + base1 + 8 * tn);
            }
        }

        // ---- S = Q K^T (Q pre-scaled) ------------------------------------
        float sc[8][4];
#pragma unroll
        for (int a = 0; a < 8; a++)
#pragma unroll
            for (int b = 0; b < 4; b++) sc[a][b] = 0.f;
#pragma unroll
        for (int s = 0; s < 4; s++)
#pragma unroll
            for (int tn = 0; tn < 8; tn++) {
                uint32_t bfr[2];
                int mr = 64 * wc + 8 * tn + g5;
                bfr[0] = Ku[mr * 36 + 8 * s + t3];
                bfr[1] = Ku[mr * 36 + 8 * s + 4 + t3];
                mma_f16(sc[tn], qf[s], bfr);
            }

        // content-score max
        float pm0 = -1e30f, pm1 = -1e30f;
#pragma unroll
        for (int tn = 0; tn < 8; tn++) {
            pm0 = fmaxf(pm0, fmaxf(sc[tn][0], sc[tn][1]));
            pm1 = fmaxf(pm1, fmaxf(sc[tn][2], sc[tn][3]));
        }
        pm0 = fmaxf(pm0, __shfl_xor_sync(~0u, pm0, 1));
        pm0 = fmaxf(pm0, __shfl_xor_sync(~0u, pm0, 2));
        pm1 = fmaxf(pm1, __shfl_xor_sync(~0u, pm1, 1));
        pm1 = fmaxf(pm1, __shfl_xor_sync(~0u, pm1, 2));
        if (t3 == 0) { sRmax[wc][rl0] = pm0; sRmax[wc][rl1] = pm1; }
        __syncthreads();

        float nm0 = fmaxf(rmax0, fmaxf(sRmax[0][rl0], sRmax[1][rl0]));
        float nm1 = fmaxf(rmax1, fmaxf(sRmax[0][rl1], sRmax[1][rl1]));
        float fs0 = __expf(rmax0 - nm0);
        float fs1 = __expf(rmax1 - nm1);
        rmax0 = nm0; rmax1 = nm1;
#pragma unroll
        for (int td = 0; td < 4; td++) {
            oc[td][0] *= fs0; oc[td][1] *= fs0;
            oc[td][2] *= fs1; oc[td][3] *= fs1;
        }

        // ---- P = w * exp(a - max), fp16 into sP -------------------------
        float ps0 = 0.f, ps1 = 0.f;
#pragma unroll
        for (int tn = 0; tn < 8; tn++) {
            float2 w0 = __half22float2(lp0[tn]);
            float2 w1 = __half22float2(lp1[tn]);
            float p0 = w0.x * __expf(sc[tn][0] - nm0);
            float p1 = w0.y * __expf(sc[tn][1] - nm0);
            float p2 = w1.x * __expf(sc[tn][2] - nm1);
            float p3 = w1.y * __expf(sc[tn][3] - nm1);
            ps0 += p0 + p1; ps1 += p2 + p3;
            int colq = 32 * wc + 4 * tn + t3;
            sP[rl0 * PP_U32 + colq] = packh2(p0, p1);
            sP[rl1 * PP_U32 + colq] = packh2(p2, p3);
        }
        ps0 += __shfl_xor_sync(~0u, ps0, 1);
        ps0 += __shfl_xor_sync(~0u, ps0, 2);
        ps1 += __shfl_xor_sync(~0u, ps1, 1);
        ps1 += __shfl_xor_sync(~0u, ps1, 2);
        if (t3 == 0) { sRsum[wc][rl0] = ps0; sRsum[wc][rl1] = ps1; }
        __syncthreads();

        rsum0 = rsum0 * fs0 + sRsum[0][rl0] + sRsum[1][rl0];
        rsum1 = rsum1 * fs1 + sRsum[0][rl1] + sRsum[1][rl1];

        // ---- O += P V ----------------------------------------------------
#pragma unroll
        for (int s = 0; s < 8; s++) {
            uint32_t af[4];
            af[0] = sP[rl0 * PP_U32 + 8 * s + t3];
            af[1] = sP[rl1 * PP_U32 + 8 * s + t3];
            af[2] = sP[rl0 * PP_U32 + 8 * s + 4 + t3];
            af[3] = sP[rl1 * PP_U32 + 8 * s + 4 + t3];
#pragma unroll
            for (int td = 0; td < 4; td++) {
                uint32_t bfr[2];
                int dcol = 32 * wc + 8 * td + g5;
                bfr[0] = Vu[dcol * 68 + 8 * s + t3];
                bfr[1] = Vu[dcol * 68 + 8 * s + 4 + t3];
                mma_f16(oc[td], af, bfr);
            }
        }
        __syncthreads();
    }

    // ---- partial epilogue -----------------------------------------------
    float* O0 = &g_O[sp][n0 + rl0][g * 64];
    float* O1 = O0 + (size_t)8 * FF;
#pragma unroll
    for (int td = 0; td < 4; td++) {
        int c = 32 * wc + 8 * td + 2 * t3;
        *(float2*)(O0 + c) = make_float2(oc[td][0], oc[td][1]);
        *(float2*)(O1 + c) = make_float2(oc[td][2], oc[td][3]);
    }
    if (t3 == 0 && wc == 0) {
        g_Mx[sp][n0 + rl0][g] = rmax0;     g_Sm[sp][n0 + rl0][g] = rsum0;
        g_Mx[sp][n0 + rl1][g] = rmax1;     g_Sm[sp][n0 + rl1][g] = rsum1;
    }
}

// ===========================================================================
// Combine the SPLIT partial outputs.
// ===========================================================================
__global__ void __launch_bounds__(256) combine_kernel(float* __restrict__ out)
{
    int idx = blockIdx.x * 256 + threadIdx.x;     // one float2 per thread
    int n = idx / (FF / 2);
    int c = (idx - n * (FF / 2)) * 2;
    int g = c >> 6;
    float m0 = g_Mx[0][n][g], m1 = g_Mx[1][n][g];
    float Mx = fmaxf(m0, m1);
    float w0 = __expf(m0 - Mx), w1 = __expf(m1 - Mx);
    float inv = 1.f / (g_Sm[0][n][g] * w0 + g_Sm[1][n][g] * w1);
    float2 a = *(const float2*)&g_O[0][n][c];
    float2 b = *(const float2*)&g_O[1][n][c];
    *(float2*)&out[(size_t)n * FF + c] =
        make_float2((a.x * w0 + b.x * w1) * inv, (a.y * w0 + b.y * w1) * inv);
}

// ===========================================================================
extern "C" void kernel_launch(void* const* d_in, const int* in_sizes, int n_in,
                              void* d_out, int out_size)
{
    (void)in_sizes; (void)n_in; (void)out_size;
    const float* bbox     = (const float*)d_in[0];
    const float* ref_bbox = (const float*)d_in[1];
    const float* roi_feat = (const float*)d_in[2];
    const float* ref_feat = (const float*)d_in[3];
    const float* Wg_w     = (const float*)d_in[4];
    const float* Wg_b     = (const float*)d_in[5];
    const float* Wq_w     = (const float*)d_in[6];
    const float* Wq_b     = (const float*)d_in[7];
    const float* Wk_w     = (const float*)d_in[8];
    const float* Wk_b     = (const float*)d_in[9];
    const float* Wv_w     = (const float*)d_in[10];  // [16,64,1024] == [1024,1024]
    const float* Wv_b     = (const float*)d_in[11];
    const float* u        = (const float*)d_in[12];  // [16,1,64] == [1024]
    float* out = (float*)d_out;

    float* Qd; __half *Kd, *VTd;
    cudaGetSymbolAddress((void**)&Qd, g_Q);
    cudaGetSymbolAddress((void**)&Kd, g_K);
    cudaGetSymbolAddress((void**)&VTd, g_VT);

    cudaFuncSetAttribute(flash_kernel,
                         cudaFuncAttributeMaxDynamicSharedMemorySize,
                         FLASH_SMEM_BYTES);

    dim3 thr(256);

    // fused prelude: pos weights (half-m quanta) + Q proj + K|V proj
    prelude_kernel<<<1312, thr>>>(bbox, ref_bbox, roi_feat, ref_feat,
                                  Wg_w, Wg_b, Wq_w, Wq_b, Wk_w, Wk_b,
                                  Wv_w, Wv_b, u, Qd, Kd, VTd);
    // fused attention (fp16 mma, split-K over m) + combine
    flash_kernel<<<dim3(NN / 64, GG, SPLIT), thr, FLASH_SMEM_BYTES>>>();
    combine_kernel<<<NN * FF / 2 / 256, thr>>>(out);
}

// round 15
// speedup vs baseline: 2.1817x; 1.0148x over previous
#include <cuda_runtime.h>
#include <cuda_fp16.h>
#include <cstdint>
#include <cstddef>

#define NN 512
#define MM 2048
#define FF 1024
#define GG 16
#define DD 64
#define SPLIT 2

// -------- scratch ----------------------------------------------------------
__device__ float  g_Q[NN * FF];                 // Q' = 0.125*(roi@Wq^T + b + u) (fp32)
__device__ __half g_K[MM * FF];                 // K  (fp16, [m][d])
__device__ __half g_VT[FF * MM];                // V^T (fp16, [d][m])
__device__ __half g_L[(size_t)NN * GG * MM];    // w = relu(Wg.emb+b)+1e-6 (fp16)
__device__ float  g_O[SPLIT][NN][FF];           // unnormalized partial outputs
__device__ float  g_Mx[SPLIT][NN][GG];          // partial content-score max
__device__ float  g_Sm[SPLIT][NN][GG];          // partial row sum
// fp16 copies of GEMM inputs (converted once; same __float2half_rn rounding
// the projection previously applied at STS time -> bit-identical results)
__device__ __half g_roi_h[NN * FF];
__device__ __half g_ref_h[MM * FF];
__device__ __half g_Wq_h[FF * FF];
__device__ __half g_Wk_h[FF * FF];
__device__ __half g_Wv_h[FF * FF];

__constant__ float c_freq[8] = {
    100.0f,        42.16965034f, 17.78279410f, 7.498942093f,
    3.162277660f,  1.333521432f, 0.5623413252f, 0.2371373706f};

__device__ __forceinline__ uint32_t f2tf32(float f) {
    uint32_t u;
    asm("cvt.rna.tf32.f32 %0, %1;" : "=r"(u) : "f"(f));
    return u;
}

__device__ __forceinline__ uint32_t packh2(float lo, float hi) {
    uint32_t r;
    asm("cvt.rn.f16x2.f32 %0, %1, %2;" : "=r"(r) : "f"(hi), "f"(lo));
    return r;
}

__device__ __forceinline__ void mma_tf32(float* c, const uint32_t* a, const uint32_t* b) {
    asm volatile(
        "mma.sync.aligned.m16n8k8.row.col.f32.tf32.tf32.f32 "
        "{%0,%1,%2,%3}, {%4,%5,%6,%7}, {%8,%9}, {%0,%1,%2,%3};"
        : "+f"(c[0]), "+f"(c[1]), "+f"(c[2]), "+f"(c[3])
        : "r"(a[0]), "r"(a[1]), "r"(a[2]), "r"(a[3]), "r"(b[0]), "r"(b[1]));
}

__device__ __forceinline__ void mma_f16(float* c, const uint32_t* a, const uint32_t* b) {
    asm volatile(
        "mma.sync.aligned.m16n8k16.row.col.f32.f16.f16.f32 "
        "{%0,%1,%2,%3}, {%4,%5,%6,%7}, {%8,%9}, {%0,%1,%2,%3};"
        : "+f"(c[0]), "+f"(c[1]), "+f"(c[2]), "+f"(c[3])
        : "r"(a[0]), "r"(a[1]), "r"(a[2]), "r"(a[3]), "r"(b[0]), "r"(b[1]));
}

__device__ __forceinline__ void ldsm_x4(uint32_t* r, uint32_t addr) {
    asm volatile("ldmatrix.sync.aligned.m8n8.x4.shared.b16 {%0,%1,%2,%3}, [%4];"
        : "=r"(r[0]), "=r"(r[1]), "=r"(r[2]), "=r"(r[3]) : "r"(addr));
}

__device__ __forceinline__ void ldsm_x2(uint32_t* r, uint32_t addr) {
    asm volatile("ldmatrix.sync.aligned.m8n8.x2.shared.b16 {%0,%1}, [%2];"
        : "=r"(r[0]), "=r"(r[1]) : "r"(addr));
}

__device__ __forceinline__ void cp16(uint32_t d, const void* s) {
    asm volatile("cp.async.cg.shared.global [%0], [%1], 16;" :: "r"(d), "l"(s));
}

// ===========================================================================
// fp32 -> fp16 conversion of all GEMM inputs (one pass, float4 granularity).
// ===========================================================================
#define SZ_ROI (NN * FF)
#define SZ_REF (MM * FF)
#define SZ_W   (FF * FF)
#define CVT_TOTAL (SZ_ROI + SZ_REF + 3 * SZ_W)      // 5,767,168
#define CVT_BLOCKS (CVT_TOTAL / 4 / 256)            // 5632

__global__ void __launch_bounds__(256) cvt_kernel(
    const float* __restrict__ roi, const float* __restrict__ ref,
    const float* __restrict__ wq, const float* __restrict__ wk,
    const float* __restrict__ wv)
{
    size_t i4 = ((size_t)blockIdx.x * 256 + threadIdx.x) * 4;
    const float* src; __half* dst; size_t off;
    if (i4 < SZ_ROI)                       { src = roi; dst = g_roi_h; off = i4; }
    else if (i4 < SZ_ROI + SZ_REF)         { src = ref; dst = g_ref_h; off = i4 - SZ_ROI; }
    else if (i4 < SZ_ROI + SZ_REF + SZ_W)  { src = wq;  dst = g_Wq_h;  off = i4 - SZ_ROI - SZ_REF; }
    else if (i4 < SZ_ROI + SZ_REF + 2*SZ_W){ src = wk;  dst = g_Wk_h;  off = i4 - SZ_ROI - SZ_REF - SZ_W; }
    else                                   { src = wv;  dst = g_Wv_h;  off = i4 - SZ_ROI - SZ_REF - 2*SZ_W; }
    float4 v = *(const float4*)(src + off);
    *(uint2*)(dst + off) = make_uint2(packh2(v.x, v.y), packh2(v.z, v.w));
}

// ===========================================================================
// Projection GEMM body, fp16 datapath (mma.m16n8k16, 128x128 tile, BK=16,
// double buffered). Inputs pre-converted to fp16: loader is 2 cp.async
// (16B) per thread per kt straight into the ldmatrix layout.
// smem pitch 12 u32 (48B) per 16-half row: ldmatrix row starts 48*i mod 128
// cover all 32 banks -> conflict-free.
// mode: 0 = fp32 [i][j]; 1 = fp16 [i][j]; 2 = fp16 T [j][i] (ld MM).
// Epilogue: v = (acc + bias) * alpha  (alpha = exact power of two).
// ===========================================================================
__device__ __noinline__ void proj_body(
    const __half* __restrict__ A, int lda,
    const __half* __restrict__ Bb, int ldb,
    void* __restrict__ Cb, int ldc,
    int Kdim, float alpha,
    const float* __restrict__ cb0, const float* __restrict__ cb1,
    int i0, int j0, int mode)
{
    __shared__ uint32_t sA[2][128 * 12];
    __shared__ uint32_t sB[2][128 * 12];

    const int t = threadIdx.x;
    const int w = t >> 5, lane = t & 31;
    const int g = lane >> 2, tig = lane & 3;
    const int wm = w & 1, wn = w >> 1;          // 2 x 4 warp grid

    const uint32_t aSmem = (uint32_t)__cvta_generic_to_shared(&sA[0][0]);
    const uint32_t bSmem = (uint32_t)__cvta_generic_to_shared(&sB[0][0]);

    // loader: one 16B chunk per thread per matrix per kt
    const int lrow = t >> 1, lhalf = (t & 1) * 8;
    const __half* aSrc = A + (size_t)(i0 + lrow) * lda + lhalf;
    const __half* bSrc = Bb + (size_t)(j0 + lrow) * ldb + lhalf;
    const uint32_t ldst = (uint32_t)(lrow * 48 + (t & 1) * 16);

    auto load_ab = [&](int buf, int kt) {
        uint32_t off = (uint32_t)(buf * 6144) + ldst;
        cp16(aSmem + off, aSrc + kt * 16);
        cp16(bSmem + off, bSrc + kt * 16);
        asm volatile("cp.async.commit_group;");
    };

    // ldmatrix per-lane base addresses (buffer 0; +6144 bytes for buffer 1)
    const uint32_t aLane = aSmem
        + (uint32_t)((wm * 64 + ((lane >> 3) & 1) * 8 + (lane & 7)) * 48
                     + ((lane & 16) ? 16 : 0));
    const uint32_t bLane = bSmem
        + (uint32_t)((wn * 32 + (lane & 7)) * 48 + ((lane & 8) ? 16 : 0));

    float acc[4][4][4];
#pragma unroll
    for (int a = 0; a < 4; a++)
#pragma unroll
        for (int b = 0; b < 4; b++)
#pragma unroll
            for (int c = 0; c < 4; c++) acc[a][b][c] = 0.f;

    const int KT = Kdim / 16;
    load_ab(0, 0);

    for (int kt = 0; kt < KT; kt++) {
        const int cur = kt & 1;
        if (kt + 1 < KT) {
            load_ab(cur ^ 1, kt + 1);
            asm volatile("cp.async.wait_group 1;");
        } else {
            asm volatile("cp.async.wait_group 0;");
        }
        __syncthreads();

        const uint32_t bufOff = (uint32_t)(cur * 6144);
        uint32_t af[4][4], bf[4][2];
#pragma unroll
        for (int tn = 0; tn < 4; tn++)
            ldsm_x2(bf[tn], bLane + bufOff + tn * 384);    // 8 rows * 48B
#pragma unroll
        for (int tm = 0; tm < 4; tm++)
            ldsm_x4(af[tm], aLane + bufOff + tm * 768);    // 16 rows * 48B
#pragma unroll
        for (int tm = 0; tm < 4; tm++)
#pragma unroll
            for (int tn = 0; tn < 4; tn++)
                mma_f16(acc[tm][tn], af[tm], bf[tn]);
        __syncthreads();                // reads done before buf reuse
    }

    // ---- epilogue: v = (acc + bias) * alpha ------------------------------
#pragma unroll
    for (int tm = 0; tm < 4; tm++) {
        int r = i0 + wm * 64 + tm * 16 + g;
#pragma unroll
        for (int tn = 0; tn < 4; tn++) {
            int c = j0 + wn * 32 + tn * 8 + tig * 2;
            float b0 = 0.f, b1 = 0.f;
            if (cb0) { b0 += cb0[c]; b1 += cb0[c + 1]; }
            if (cb1) { b0 += cb1[c]; b1 += cb1[c + 1]; }
            float v0 = (acc[tm][tn][0] + b0) * alpha;
            float v1 = (acc[tm][tn][1] + b1) * alpha;
            float v2 = (acc[tm][tn][2] + b0) * alpha;
            float v3 = (acc[tm][tn][3] + b1) * alpha;
            if (mode == 0) {
                float* Cf = (float*)Cb;
                *(float2*)(Cf + (size_t)r * ldc + c) = make_float2(v0, v1);
                *(float2*)(Cf + (size_t)(r + 8) * ldc + c) = make_float2(v2, v3);
            } else if (mode == 1) {
                __half* Ch = (__half*)Cb;
                *(uint32_t*)(Ch + (size_t)r * ldc + c) = packh2(v0, v1);
                *(uint32_t*)(Ch + (size_t)(r + 8) * ldc + c) = packh2(v2, v3);
            } else {
                __half* Ch = (__half*)Cb;        // [j][i], stride MM
                Ch[(size_t)c * MM + r]           = __float2half_rn(v0);
                Ch[(size_t)(c + 1) * MM + r]     = __float2half_rn(v1);
                Ch[(size_t)c * MM + r + 8]       = __float2half_rn(v2);
                Ch[(size_t)(c + 1) * MM + r + 8] = __float2half_rn(v3);
            }
        }
    }
}

// ===========================================================================
// pos body: w[n][g][m] = relu(emb(n,m,:)·Wg[g,:]+b) + 1e-6, fp16 out.
// One block covers HALF the m-range (mh in {0,1}) for one n.
// ===========================================================================
__device__ __noinline__ void pos_body(
    int n, int mh,
    const float* __restrict__ bbox, const float* __restrict__ ref_bbox,
    const float* __restrict__ Wg_w, const float* __restrict__ Wg_b)
{
    const int t = threadIdx.x;
    const int w = t >> 5, lane = t & 31;
    const int g5 = lane >> 2, t3 = lane & 3;

    float x0 = bbox[n * 4 + 0], y0 = bbox[n * 4 + 1];
    float x1 = bbox[n * 4 + 2], y1 = bbox[n * 4 + 3];
    float bw = x1 - x0 + 1.f, bh = y1 - y0 + 1.f;
    float cx = 0.5f * (x0 + x1), cy = 0.5f * (y0 + y1);
    float iw = 1.f / bw, ih = 1.f / bh;
    float lw = __logf(bw), lh = __logf(bh);

    uint32_t breg[2][8][2];
#pragma unroll
    for (int tt = 0; tt < 2; tt++)
#pragma unroll
        for (int s = 0; s < 8; s++) {
            breg[tt][s][0] = f2tf32(Wg_w[(8 * tt + g5) * 64 + 8 * s + t3]);
            breg[tt][s][1] = f2tf32(Wg_w[(8 * tt + g5) * 64 + 8 * s + 4 + t3]);
        }
    float bias[2][2];
#pragma unroll
    for (int tt = 0; tt < 2; tt++) {
        bias[tt][0] = Wg_b[8 * tt + 2 * t3];
        bias[tt][1] = Wg_b[8 * tt + 2 * t3 + 1];
    }
    const float fr0 = c_freq[t3], fr1 = c_freq[t3 + 4];

    __half* Lpn = g_L + (size_t)n * GG * MM;

    for (int it = 0; it < 8; it++) {
        const int mbase = (mh * 64 + it * 8 + w) * 16;
        const int m0p = mbase + g5, m1p = m0p + 8;

        float4 rb0 = *(const float4*)(ref_bbox + (size_t)m0p * 4);
        float4 rb1 = *(const float4*)(ref_bbox + (size_t)m1p * 4);
        float p0[4], p1[4];
        {
            float wr = rb0.z - rb0.x + 1.f, hr = rb0.w - rb0.y + 1.f;
            float cxr = 0.5f * (rb0.x + rb0.z), cyr = 0.5f * (rb0.y + rb0.w);
            p0[0] = __logf(fabsf((cx - cxr) * iw) + 1e-3f);
            p0[1] = __logf(fabsf((cy - cyr) * ih) + 1e-3f);
            p0[2] = lw - __logf(wr);
            p0[3] = lh - __logf(hr);
        }
        {
            float wr = rb1.z - rb1.x + 1.f, hr = rb1.w - rb1.y + 1.f;
            float cxr = 0.5f * (rb1.x + rb1.z), cyr = 0.5f * (rb1.y + rb1.w);
            p1[0] = __logf(fabsf((cx - cxr) * iw) + 1e-3f);
            p1[1] = __logf(fabsf((cy - cyr) * ih) + 1e-3f);
            p1[2] = lw - __logf(wr);
            p1[3] = lh - __logf(hr);
        }

        float ct[2][4];
#pragma unroll
        for (int tt = 0; tt < 2; tt++)
#pragma unroll
            for (int j = 0; j < 4; j++) ct[tt][j] = 0.f;

#pragma unroll
        for (int c = 0; c < 4; c++) {
            float s00, c00, s01, c01, s10, c10, s11, c11;
            __sincosf(p0[c] * fr0, &s00, &c00);
            __sincosf(p0[c] * fr1, &s01, &c01);
            __sincosf(p1[c] * fr0, &s10, &c10);
            __sincosf(p1[c] * fr1, &s11, &c11);
            uint32_t asin_[4] = {f2tf32(s00), f2tf32(s10), f2tf32(s01), f2tf32(s11)};
            uint32_t acos_[4] = {f2tf32(c00), f2tf32(c10), f2tf32(c01), f2tf32(c11)};
            mma_tf32(ct[0], asin_, breg[0][2 * c]);
            mma_tf32(ct[1], asin_, breg[1][2 * c]);
            mma_tf32(ct[0], acos_, breg[0][2 * c + 1]);
            mma_tf32(ct[1], acos_, breg[1][2 * c + 1]);
        }

#pragma unroll
        for (int tt = 0; tt < 2; tt++) {
            int gc = 8 * tt + 2 * t3;
            float v0 = fmaxf(ct[tt][0] + bias[tt][0], 0.f) + 1e-6f;
            float v1 = fmaxf(ct[tt][1] + bias[tt][1], 0.f) + 1e-6f;
            float v2 = fmaxf(ct[tt][2] + bias[tt][0], 0.f) + 1e-6f;
            float v3 = fmaxf(ct[tt][3] + bias[tt][1], 0.f) + 1e-6f;
            Lpn[(size_t)gc * MM + m0p]       = __float2half_rn(v0);
            Lpn[(size_t)(gc + 1) * MM + m0p] = __float2half_rn(v1);
            Lpn[(size_t)gc * MM + m1p]       = __float2half_rn(v2);
            Lpn[(size_t)(gc + 1) * MM + m1p] = __float2half_rn(v3);
        }
    }
}

// ===========================================================================
// Prelude dispatcher: 1312 blocks (R12 mapping).
//   bid < 576: even -> proj(bid/2) [0..287], odd -> pos chunk bid/2 [0..287]
//   bid >= 576: pos chunk (bid - 288)        [288..1023]
// pos chunk id c: n = c >> 1, mh = c & 1.
// proj id p: p < 32 -> Q projection (grid 8x4); else p-32 -> K|V (grid 16x16).
// ===========================================================================
__global__ void __launch_bounds__(256, 2) prelude_kernel(
    const float* __restrict__ bbox, const float* __restrict__ ref_bbox,
    const float* __restrict__ Wg_w, const float* __restrict__ Wg_b,
    const float* __restrict__ Wq_b, const float* __restrict__ Wk_b,
    const float* __restrict__ Wv_b, const float* __restrict__ u,
    float* __restrict__ Qd, __half* __restrict__ Kd, __half* __restrict__ VTd)
{
    const int bid = blockIdx.x;
    int proj = -1, posc = -1;
    if (bid < 576) {
        if ((bid & 1) == 0) proj = bid >> 1;
        else posc = bid >> 1;
    } else {
        posc = bid - 288;
    }

    if (posc >= 0) {
        pos_body(posc >> 1, posc & 1, bbox, ref_bbox, Wg_w, Wg_b);
        return;
    }

    const __half *A, *B;
    const float *cb0, *cb1 = nullptr;
    void* C;
    int i0, j0, mode;
    float alpha;
    if (proj < 32) {                 // Q projection: grid 8 x 4 over (FF, NN)
        int bx = proj & 7, by = proj >> 3;
        A = g_roi_h; B = g_Wq_h; C = Qd; cb0 = Wq_b; cb1 = u;
        i0 = by * 128; j0 = bx * 128; mode = 0; alpha = 0.125f;
    } else {                         // K|V projection: grid 16 x 16 over (2FF, MM)
        int p = proj - 32;
        int bx = p & 15, by = p >> 4;
        A = g_ref_h;
        i0 = by * 128; j0 = bx * 128; alpha = 1.f;
        if (j0 < FF) { B = g_Wk_h; C = Kd; cb0 = Wk_b; mode = 1; }
        else         { B = g_Wv_h; C = VTd; cb0 = Wv_b; mode = 2; j0 -= FF; }
    }
    proj_body(A, FF, B, FF, C, FF, FF, alpha, cb0, cb1, i0, j0, mode);
}

// ===========================================================================
// Flash attention (fp16 mma): block = (n-tile 64, head g, split). 2 blocks/SM.
// Q is pre-scaled by 0.125 at projection time (exact power of two).
// ===========================================================================
#define KB_U32 (128 * 36)
#define VB_U32 (64 * 68)
#define PP_U32 68
#define FLASH_SMEM_BYTES ((2 * KB_U32 + 2 * VB_U32 + 64 * PP_U32) * 4)
#define FL_TILES ((MM / SPLIT) / 128)   // 8

__global__ void __launch_bounds__(256, 2) flash_kernel()
{
    extern __shared__ uint32_t smem[];
    uint32_t* sK = smem;                           // [2][128][36] u32
    uint32_t* sV = smem + 2 * KB_U32;              // [2][64][68] u32
    uint32_t* sP = smem + 2 * KB_U32 + 2 * VB_U32; // [64][68] u32

    __shared__ float sRmax[2][64];
    __shared__ float sRsum[2][64];

    const int t = threadIdx.x;
    const int w = t >> 5, lane = t & 31;
    const int g5 = lane >> 2, t3 = lane & 3;
    const int wr = w & 3, wc = w >> 2;
    const int n0 = blockIdx.x * 64;
    const int g = blockIdx.y;
    const int sp = blockIdx.z;
    const int m_base = sp * (MM / SPLIT);

    const uint32_t kb = (uint32_t)__cvta_generic_to_shared(sK);
    const uint32_t vb = (uint32_t)__cvta_generic_to_shared(sV);

    // ---- Q tile (64x64 fp32, pre-scaled) -> staging -> fp16 fragments ---
    {
        float* sPf = (float*)sP;                 // pitch 68 floats
#pragma unroll
        for (int i = 0; i < 4; i++) {
            int f = t + i * 256;
            int row = f >> 4, c4 = (f & 15) << 2;
            *(float4*)&sPf[row * 68 + c4] =
                *(const float4*)(g_Q + (size_t)(n0 + row) * FF + g * 64 + c4);
        }
    }
    __syncthreads();
    const int rl0 = 16 * wr + g5, rl1 = rl0 + 8;
    uint32_t qf[4][4];
    {
        const float* sPf = (const float*)sP;
        int r = 16 * wr + g5;
#pragma unroll
        for (int s = 0; s < 4; s++) {
            float2 x0 = *(const float2*)&sPf[r * 68 + 16 * s + 2 * t3];
            float2 x1 = *(const float2*)&sPf[(r + 8) * 68 + 16 * s + 2 * t3];
            float2 x2 = *(const float2*)&sPf[r * 68 + 16 * s + 2 * t3 + 8];
            float2 x3 = *(const float2*)&sPf[(r + 8) * 68 + 16 * s + 2 * t3 + 8];
            qf[s][0] = packh2(x0.x, x0.y);
            qf[s][1] = packh2(x1.x, x1.y);
            qf[s][2] = packh2(x2.x, x2.y);
            qf[s][3] = packh2(x3.x, x3.y);
        }
    }

    // ---- K / V^T tile loaders (cp.async, fp16) --------------------------
    auto load_kv = [&](int buf, int m0) {
#pragma unroll
        for (int i = 0; i < 4; i++) {            // K: 128 rows x 128B
            int f = t + i * 256;
            int row = f >> 3, h8 = (f & 7) * 8;
            cp16(kb + (uint32_t)((buf * KB_U32 + row * 36) * 4 + h8 * 2),
                 g_K + (size_t)(m0 + row) * FF + g * 64 + h8);
        }
#pragma unroll
        for (int i = 0; i < 4; i++) {            // VT: 64 rows x 256B
            int f = t + i * 256;
            int row = f >> 4, h8 = (f & 15) * 8;
            cp16(vb + (uint32_t)((buf * VB_U32 + row * 68) * 4 + h8 * 2),
                 g_VT + (size_t)(g * 64 + row) * MM + m0 + h8);
        }
        asm volatile("cp.async.commit_group;");
    };

    load_kv(0, m_base);
    __syncthreads();   // Q staging in sP consumed before first P write

    float rmax0 = -1e30f, rmax1 = -1e30f, rsum0 = 0.f, rsum1 = 0.f;
    float oc[4][4];
#pragma unroll
    for (int a = 0; a < 4; a++)
#pragma unroll
        for (int b = 0; b < 4; b++) oc[a][b] = 0.f;

    for (int mt = 0; mt < FL_TILES; mt++) {
        if (mt + 1 < FL_TILES) {
            load_kv((mt + 1) & 1, m_base + (mt + 1) * 128);
            asm volatile("cp.async.wait_group 1;");
        } else {
            asm volatile("cp.async.wait_group 0;");
        }
        __syncthreads();

        const uint32_t* Ku = sK + (mt & 1) * KB_U32;
        const uint32_t* Vu = sV + (mt & 1) * VB_U32;

        // pos weights (fp16, multiplicative)
        __half2 lp0[8], lp1[8];
        {
            size_t base0 = ((size_t)(n0 + rl0) * GG + g) * MM
                         + m_base + mt * 128 + 64 * wc + 2 * t3;
            size_t base1 = base0 + (size_t)8 * GG * MM;
#pragma unroll
            for (int tn = 0; tn < 8; tn++) {
                lp0[tn] = *(const __half2*)(g_L + base0 + 8 * tn);
                lp1[tn] = *(const __half2*)(g_L + base1 + 8 * tn);
            }
        }

        // ---- S = Q K^T (Q pre-scaled) ------------------------------------
        float sc[8][4];
#pragma unroll
        for (int a = 0; a < 8; a++)
#pragma unroll
            for (int b = 0; b < 4; b++) sc[a][b] = 0.f;
#pragma unroll
        for (int s = 0; s < 4; s++)
#pragma unroll
            for (int tn = 0; tn < 8; tn++) {
                uint32_t bfr[2];
                int mr = 64 * wc + 8 * tn + g5;
                bfr[0] = Ku[mr * 36 + 8 * s + t3];
                bfr[1] = Ku[mr * 36 + 8 * s + 4 + t3];
                mma_f16(sc[tn], qf[s], bfr);
            }

        // content-score max
        float pm0 = -1e30f, pm1 = -1e30f;
#pragma unroll
        for (int tn = 0; tn < 8; tn++) {
            pm0 = fmaxf(pm0, fmaxf(sc[tn][0], sc[tn][1]));
            pm1 = fmaxf(pm1, fmaxf(sc[tn][2], sc[tn][3]));
        }
        pm0 = fmaxf(pm0, __shfl_xor_sync(~0u, pm0, 1));
        pm0 = fmaxf(pm0, __shfl_xor_sync(~0u, pm0, 2));
        pm1 = fmaxf(pm1, __shfl_xor_sync(~0u, pm1, 1));
        pm1 = fmaxf(pm1, __shfl_xor_sync(~0u, pm1, 2));
        if (t3 == 0) { sRmax[wc][rl0] = pm0; sRmax[wc][rl1] = pm1; }
        __syncthreads();

        float nm0 = fmaxf(rmax0, fmaxf(sRmax[0][rl0], sRmax[1][rl0]));
        float nm1 = fmaxf(rmax1, fmaxf(sRmax[0][rl1], sRmax[1][rl1]));
        float fs0 = __expf(rmax0 - nm0);
        float fs1 = __expf(rmax1 - nm1);
        rmax0 = nm0; rmax1 = nm1;
#pragma unroll
        for (int td = 0; td < 4; td++) {
            oc[td][0] *= fs0; oc[td][1] *= fs0;
            oc[td][2] *= fs1; oc[td][3] *= fs1;
        }

        // ---- P = w * exp(a - max), fp16 into sP -------------------------
        float ps0 = 0.f, ps1 = 0.f;
#pragma unroll
        for (int tn = 0; tn < 8; tn++) {
            float2 w0 = __half22float2(lp0[tn]);
            float2 w1 = __half22float2(lp1[tn]);
            float p0 = w0.x * __expf(sc[tn][0] - nm0);
            float p1 = w0.y * __expf(sc[tn][1] - nm0);
            float p2 = w1.x * __expf(sc[tn][2] - nm1);
            float p3 = w1.y * __expf(sc[tn][3] - nm1);
            ps0 += p0 + p1; ps1 += p2 + p3;
            int colq = 32 * wc + 4 * tn + t3;
            sP[rl0 * PP_U32 + colq] = packh2(p0, p1);
            sP[rl1 * PP_U32 + colq] = packh2(p2, p3);
        }
        ps0 += __shfl_xor_sync(~0u, ps0, 1);
        ps0 += __shfl_xor_sync(~0u, ps0, 2);
        ps1 += __shfl_xor_sync(~0u, ps1, 1);
        ps1 += __shfl_xor_sync(~0u, ps1, 2);
        if (t3 == 0) { sRsum[wc][rl0] = ps0; sRsum[wc][rl1] = ps1; }
        __syncthreads();

        rsum0 = rsum0 * fs0 + sRsum[0][rl0] + sRsum[1][rl0];
        rsum1 = rsum1 * fs1 + sRsum[0][rl1] + sRsum[1][rl1];

        // ---- O += P V ----------------------------------------------------
#pragma unroll
        for (int s = 0; s < 8; s++) {
            uint32_t af[4];
            af[0] = sP[rl0 * PP_U32 + 8 * s + t3];
            af[1] = sP[rl1 * PP_U32 + 8 * s + t3];
            af[2] = sP[rl0 * PP_U32 + 8 * s + 4 + t3];
            af[3] = sP[rl1 * PP_U32 + 8 * s + 4 + t3];
#pragma unroll
            for (int td = 0; td < 4; td++) {
                uint32_t bfr[2];
                int dcol = 32 * wc + 8 * td + g5;
                bfr[0] = Vu[dcol * 68 + 8 * s + t3];
                bfr[1] = Vu[dcol * 68 + 8 * s + 4 + t3];
                mma_f16(oc[td], af, bfr);
            }
        }
        __syncthreads();
    }

    // ---- partial epilogue -----------------------------------------------
    float* O0 = &g_O[sp][n0 + rl0][g * 64];
    float* O1 = O0 + (size_t)8 * FF;
#pragma unroll
    for (int td = 0; td < 4; td++) {
        int c = 32 * wc + 8 * td + 2 * t3;
        *(float2*)(O0 + c) = make_float2(oc[td][0], oc[td][1]);
        *(float2*)(O1 + c) = make_float2(oc[td][2], oc[td][3]);
    }
    if (t3 == 0 && wc == 0) {
        g_Mx[sp][n0 + rl0][g] = rmax0;     g_Sm[sp][n0 + rl0][g] = rsum0;
        g_Mx[sp][n0 + rl1][g] = rmax1;     g_Sm[sp][n0 + rl1][g] = rsum1;
    }
}

// ===========================================================================
// Combine the SPLIT partial outputs.
// ===========================================================================
__global__ void __launch_bounds__(256) combine_kernel(float* __restrict__ out)
{
    int idx = blockIdx.x * 256 + threadIdx.x;     // one float2 per thread
    int n = idx / (FF / 2);
    int c = (idx - n * (FF / 2)) * 2;
    int g = c >> 6;
    float m0 = g_Mx[0][n][g], m1 = g_Mx[1][n][g];
    float Mx = fmaxf(m0, m1);
    float w0 = __expf(m0 - Mx), w1 = __expf(m1 - Mx);
    float inv = 1.f / (g_Sm[0][n][g] * w0 + g_Sm[1][n][g] * w1);
    float2 a = *(const float2*)&g_O[0][n][c];
    float2 b = *(const float2*)&g_O[1][n][c];
    *(float2*)&out[(size_t)n * FF + c] =
        make_float2((a.x * w0 + b.x * w1) * inv, (a.y * w0 + b.y * w1) * inv);
}

// ===========================================================================
extern "C" void kernel_launch(void* const* d_in, const int* in_sizes, int n_in,
                              void* d_out, int out_size)
{
    (void)in_sizes; (void)n_in; (void)out_size;
    const float* bbox     = (const float*)d_in[0];
    const float* ref_bbox = (const float*)d_in[1];
    const float* roi_feat = (const float*)d_in[2];
    const float* ref_feat = (const float*)d_in[3];
    const float* Wg_w     = (const float*)d_in[4];
    const float* Wg_b     = (const float*)d_in[5];
    const float* Wq_w     = (const float*)d_in[6];
    const float* Wq_b     = (const float*)d_in[7];
    const float* Wk_w     = (const float*)d_in[8];
    const float* Wk_b     = (const float*)d_in[9];
    const float* Wv_w     = (const float*)d_in[10];  // [16,64,1024] == [1024,1024]
    const float* Wv_b     = (const float*)d_in[11];
    const float* u        = (const float*)d_in[12];  // [16,1,64] == [1024]
    float* out = (float*)d_out;

    float* Qd; __half *Kd, *VTd;
    cudaGetSymbolAddress((void**)&Qd, g_Q);
    cudaGetSymbolAddress((void**)&Kd, g_K);
    cudaGetSymbolAddress((void**)&VTd, g_VT);

    cudaFuncSetAttribute(flash_kernel,
                         cudaFuncAttributeMaxDynamicSharedMemorySize,
                         FLASH_SMEM_BYTES);

    dim3 thr(256);

    // one-pass fp32 -> fp16 conversion of all GEMM inputs
    cvt_kernel<<<CVT_BLOCKS, thr>>>(roi_feat, ref_feat, Wq_w, Wk_w, Wv_w);
    // fused prelude: pos weights (half-m quanta) + Q proj + K|V proj
    prelude_kernel<<<1312, thr>>>(bbox, ref_bbox, Wg_w, Wg_b,
                                  Wq_b, Wk_b, Wv_b, u, Qd, Kd, VTd);
    // fused attention (fp16 mma, split-K over m) + combine
    flash_kernel<<<dim3(NN / 64, GG, SPLIT), thr, FLASH_SMEM_BYTES>>>();
    combine_kernel<<<NN * FF / 2 / 256, thr>>>(out);
}

// round 16
// speedup vs baseline: 2.2145x; 1.0150x over previous
#include <cuda_runtime.h>
#include <cuda_fp16.h>
#include <cstdint>
#include <cstddef>

#define NN 512
#define MM 2048
#define FF 1024
#define GG 16
#define DD 64
#define SPLIT 2

// -------- scratch ----------------------------------------------------------
__device__ float  g_Q[NN * FF];                 // Q' = 0.125*(roi@Wq^T + b + u) (fp32)
__device__ __half g_K[MM * FF];                 // K  (fp16, [m][d])
__device__ __half g_VT[FF * MM];                // V^T (fp16, [d][m])
__device__ __half g_L[(size_t)NN * GG * MM];    // w = relu(Wg.emb+b)+1e-6 (fp16)
__device__ float  g_O[SPLIT][NN][FF];           // unnormalized partial outputs
__device__ float  g_Mx[SPLIT][NN][GG];          // partial content-score max
__device__ float  g_Sm[SPLIT][NN][GG];          // partial row sum
// fp16 copies of GEMM inputs (converted once)
__device__ __half g_roi_h[NN * FF];
__device__ __half g_ref_h[MM * FF];
__device__ __half g_Wq_h[FF * FF];
__device__ __half g_Wk_h[FF * FF];
__device__ __half g_Wv_h[FF * FF];

__constant__ float c_freq[8] = {
    100.0f,        42.16965034f, 17.78279410f, 7.498942093f,
    3.162277660f,  1.333521432f, 0.5623413252f, 0.2371373706f};

__device__ __forceinline__ uint32_t f2tf32(float f) {
    uint32_t u;
    asm("cvt.rna.tf32.f32 %0, %1;" : "=r"(u) : "f"(f));
    return u;
}

__device__ __forceinline__ uint32_t packh2(float lo, float hi) {
    uint32_t r;
    asm("cvt.rn.f16x2.f32 %0, %1, %2;" : "=r"(r) : "f"(hi), "f"(lo));
    return r;
}

__device__ __forceinline__ void mma_tf32(float* c, const uint32_t* a, const uint32_t* b) {
    asm volatile(
        "mma.sync.aligned.m16n8k8.row.col.f32.tf32.tf32.f32 "
        "{%0,%1,%2,%3}, {%4,%5,%6,%7}, {%8,%9}, {%0,%1,%2,%3};"
        : "+f"(c[0]), "+f"(c[1]), "+f"(c[2]), "+f"(c[3])
        : "r"(a[0]), "r"(a[1]), "r"(a[2]), "r"(a[3]), "r"(b[0]), "r"(b[1]));
}

__device__ __forceinline__ void mma_f16(float* c, const uint32_t* a, const uint32_t* b) {
    asm volatile(
        "mma.sync.aligned.m16n8k16.row.col.f32.f16.f16.f32 "
        "{%0,%1,%2,%3}, {%4,%5,%6,%7}, {%8,%9}, {%0,%1,%2,%3};"
        : "+f"(c[0]), "+f"(c[1]), "+f"(c[2]), "+f"(c[3])
        : "r"(a[0]), "r"(a[1]), "r"(a[2]), "r"(a[3]), "r"(b[0]), "r"(b[1]));
}

__device__ __forceinline__ void ldsm_x4(uint32_t* r, uint32_t addr) {
    asm volatile("ldmatrix.sync.aligned.m8n8.x4.shared.b16 {%0,%1,%2,%3}, [%4];"
        : "=r"(r[0]), "=r"(r[1]), "=r"(r[2]), "=r"(r[3]) : "r"(addr));
}

__device__ __forceinline__ void ldsm_x2(uint32_t* r, uint32_t addr) {
    asm volatile("ldmatrix.sync.aligned.m8n8.x2.shared.b16 {%0,%1}, [%2];"
        : "=r"(r[0]), "=r"(r[1]) : "r"(addr));
}

__device__ __forceinline__ void cp16(uint32_t d, const void* s) {
    asm volatile("cp.async.cg.shared.global [%0], [%1], 16;" :: "r"(d), "l"(s));
}

// ===========================================================================
// fp32 -> fp16 conversion of all GEMM inputs (one pass, float4 granularity).
// ===========================================================================
#define SZ_ROI (NN * FF)
#define SZ_REF (MM * FF)
#define SZ_W   (FF * FF)
#define CVT_TOTAL (SZ_ROI + SZ_REF + 3 * SZ_W)
#define CVT_BLOCKS (CVT_TOTAL / 4 / 256)

__global__ void __launch_bounds__(256) cvt_kernel(
    const float* __restrict__ roi, const float* __restrict__ ref,
    const float* __restrict__ wq, const float* __restrict__ wk,
    const float* __restrict__ wv)
{
    size_t i4 = ((size_t)blockIdx.x * 256 + threadIdx.x) * 4;
    const float* src; __half* dst; size_t off;
    if (i4 < SZ_ROI)                       { src = roi; dst = g_roi_h; off = i4; }
    else if (i4 < SZ_ROI + SZ_REF)         { src = ref; dst = g_ref_h; off = i4 - SZ_ROI; }
    else if (i4 < SZ_ROI + SZ_REF + SZ_W)  { src = wq;  dst = g_Wq_h;  off = i4 - SZ_ROI - SZ_REF; }
    else if (i4 < SZ_ROI + SZ_REF + 2*SZ_W){ src = wk;  dst = g_Wk_h;  off = i4 - SZ_ROI - SZ_REF - SZ_W; }
    else                                   { src = wv;  dst = g_Wv_h;  off = i4 - SZ_ROI - SZ_REF - 2*SZ_W; }
    float4 v = *(const float4*)(src + off);
    *(uint2*)(dst + off) = make_uint2(packh2(v.x, v.y), packh2(v.z, v.w));
}

// ===========================================================================
// Projection GEMM body (R15, unchanged): fp16 mma, cp.async loader, ldmatrix.
// ===========================================================================
__device__ __noinline__ void proj_body(
    const __half* __restrict__ A, int lda,
    const __half* __restrict__ Bb, int ldb,
    void* __restrict__ Cb, int ldc,
    int Kdim, float alpha,
    const float* __restrict__ cb0, const float* __restrict__ cb1,
    int i0, int j0, int mode)
{
    __shared__ uint32_t sA[2][128 * 12];
    __shared__ uint32_t sB[2][128 * 12];

    const int t = threadIdx.x;
    const int w = t >> 5, lane = t & 31;
    const int g = lane >> 2, tig = lane & 3;
    const int wm = w & 1, wn = w >> 1;

    const uint32_t aSmem = (uint32_t)__cvta_generic_to_shared(&sA[0][0]);
    const uint32_t bSmem = (uint32_t)__cvta_generic_to_shared(&sB[0][0]);

    const int lrow = t >> 1, lhalf = (t & 1) * 8;
    const __half* aSrc = A + (size_t)(i0 + lrow) * lda + lhalf;
    const __half* bSrc = Bb + (size_t)(j0 + lrow) * ldb + lhalf;
    const uint32_t ldst = (uint32_t)(lrow * 48 + (t & 1) * 16);

    auto load_ab = [&](int buf, int kt) {
        uint32_t off = (uint32_t)(buf * 6144) + ldst;
        cp16(aSmem + off, aSrc + kt * 16);
        cp16(bSmem + off, bSrc + kt * 16);
        asm volatile("cp.async.commit_group;");
    };

    const uint32_t aLane = aSmem
        + (uint32_t)((wm * 64 + ((lane >> 3) & 1) * 8 + (lane & 7)) * 48
                     + ((lane & 16) ? 16 : 0));
    const uint32_t bLane = bSmem
        + (uint32_t)((wn * 32 + (lane & 7)) * 48 + ((lane & 8) ? 16 : 0));

    float acc[4][4][4];
#pragma unroll
    for (int a = 0; a < 4; a++)
#pragma unroll
        for (int b = 0; b < 4; b++)
#pragma unroll
            for (int c = 0; c < 4; c++) acc[a][b][c] = 0.f;

    const int KT = Kdim / 16;
    load_ab(0, 0);

    for (int kt = 0; kt < KT; kt++) {
        const int cur = kt & 1;
        if (kt + 1 < KT) {
            load_ab(cur ^ 1, kt + 1);
            asm volatile("cp.async.wait_group 1;");
        } else {
            asm volatile("cp.async.wait_group 0;");
        }
        __syncthreads();

        const uint32_t bufOff = (uint32_t)(cur * 6144);
        uint32_t af[4][4], bf[4][2];
#pragma unroll
        for (int tn = 0; tn < 4; tn++)
            ldsm_x2(bf[tn], bLane + bufOff + tn * 384);
#pragma unroll
        for (int tm = 0; tm < 4; tm++)
            ldsm_x4(af[tm], aLane + bufOff + tm * 768);
#pragma unroll
        for (int tm = 0; tm < 4; tm++)
#pragma unroll
            for (int tn = 0; tn < 4; tn++)
                mma_f16(acc[tm][tn], af[tm], bf[tn]);
        __syncthreads();
    }

#pragma unroll
    for (int tm = 0; tm < 4; tm++) {
        int r = i0 + wm * 64 + tm * 16 + g;
#pragma unroll
        for (int tn = 0; tn < 4; tn++) {
            int c = j0 + wn * 32 + tn * 8 + tig * 2;
            float b0 = 0.f, b1 = 0.f;
            if (cb0) { b0 += cb0[c]; b1 += cb0[c + 1]; }
            if (cb1) { b0 += cb1[c]; b1 += cb1[c + 1]; }
            float v0 = (acc[tm][tn][0] + b0) * alpha;
            float v1 = (acc[tm][tn][1] + b1) * alpha;
            float v2 = (acc[tm][tn][2] + b0) * alpha;
            float v3 = (acc[tm][tn][3] + b1) * alpha;
            if (mode == 0) {
                float* Cf = (float*)Cb;
                *(float2*)(Cf + (size_t)r * ldc + c) = make_float2(v0, v1);
                *(float2*)(Cf + (size_t)(r + 8) * ldc + c) = make_float2(v2, v3);
            } else if (mode == 1) {
                __half* Ch = (__half*)Cb;
                *(uint32_t*)(Ch + (size_t)r * ldc + c) = packh2(v0, v1);
                *(uint32_t*)(Ch + (size_t)(r + 8) * ldc + c) = packh2(v2, v3);
            } else {
                __half* Ch = (__half*)Cb;        // [j][i], stride MM
                Ch[(size_t)c * MM + r]           = __float2half_rn(v0);
                Ch[(size_t)(c + 1) * MM + r]     = __float2half_rn(v1);
                Ch[(size_t)c * MM + r + 8]       = __float2half_rn(v2);
                Ch[(size_t)(c + 1) * MM + r + 8] = __float2half_rn(v3);
            }
        }
    }
}

// ===========================================================================
// pos body (unchanged): w = relu(Wg.emb+b)+1e-6, fp16 out, half-m quanta.
// ===========================================================================
__device__ __noinline__ void pos_body(
    int n, int mh,
    const float* __restrict__ bbox, const float* __restrict__ ref_bbox,
    const float* __restrict__ Wg_w, const float* __restrict__ Wg_b)
{
    const int t = threadIdx.x;
    const int w = t >> 5, lane = t & 31;
    const int g5 = lane >> 2, t3 = lane & 3;

    float x0 = bbox[n * 4 + 0], y0 = bbox[n * 4 + 1];
    float x1 = bbox[n * 4 + 2], y1 = bbox[n * 4 + 3];
    float bw = x1 - x0 + 1.f, bh = y1 - y0 + 1.f;
    float cx = 0.5f * (x0 + x1), cy = 0.5f * (y0 + y1);
    float iw = 1.f / bw, ih = 1.f / bh;
    float lw = __logf(bw), lh = __logf(bh);

    uint32_t breg[2][8][2];
#pragma unroll
    for (int tt = 0; tt < 2; tt++)
#pragma unroll
        for (int s = 0; s < 8; s++) {
            breg[tt][s][0] = f2tf32(Wg_w[(8 * tt + g5) * 64 + 8 * s + t3]);
            breg[tt][s][1] = f2tf32(Wg_w[(8 * tt + g5) * 64 + 8 * s + 4 + t3]);
        }
    float bias[2][2];
#pragma unroll
    for (int tt = 0; tt < 2; tt++) {
        bias[tt][0] = Wg_b[8 * tt + 2 * t3];
        bias[tt][1] = Wg_b[8 * tt + 2 * t3 + 1];
    }
    const float fr0 = c_freq[t3], fr1 = c_freq[t3 + 4];

    __half* Lpn = g_L + (size_t)n * GG * MM;

    for (int it = 0; it < 8; it++) {
        const int mbase = (mh * 64 + it * 8 + w) * 16;
        const int m0p = mbase + g5, m1p = m0p + 8;

        float4 rb0 = *(const float4*)(ref_bbox + (size_t)m0p * 4);
        float4 rb1 = *(const float4*)(ref_bbox + (size_t)m1p * 4);
        float p0[4], p1[4];
        {
            float wr = rb0.z - rb0.x + 1.f, hr = rb0.w - rb0.y + 1.f;
            float cxr = 0.5f * (rb0.x + rb0.z), cyr = 0.5f * (rb0.y + rb0.w);
            p0[0] = __logf(fabsf((cx - cxr) * iw) + 1e-3f);
            p0[1] = __logf(fabsf((cy - cyr) * ih) + 1e-3f);
            p0[2] = lw - __logf(wr);
            p0[3] = lh - __logf(hr);
        }
        {
            float wr = rb1.z - rb1.x + 1.f, hr = rb1.w - rb1.y + 1.f;
            float cxr = 0.5f * (rb1.x + rb1.z), cyr = 0.5f * (rb1.y + rb1.w);
            p1[0] = __logf(fabsf((cx - cxr) * iw) + 1e-3f);
            p1[1] = __logf(fabsf((cy - cyr) * ih) + 1e-3f);
            p1[2] = lw - __logf(wr);
            p1[3] = lh - __logf(hr);
        }

        float ct[2][4];
#pragma unroll
        for (int tt = 0; tt < 2; tt++)
#pragma unroll
            for (int j = 0; j < 4; j++) ct[tt][j] = 0.f;

#pragma unroll
        for (int c = 0; c < 4; c++) {
            float s00, c00, s01, c01, s10, c10, s11, c11;
            __sincosf(p0[c] * fr0, &s00, &c00);
            __sincosf(p0[c] * fr1, &s01, &c01);
            __sincosf(p1[c] * fr0, &s10, &c10);
            __sincosf(p1[c] * fr1, &s11, &c11);
            uint32_t asin_[4] = {f2tf32(s00), f2tf32(s10), f2tf32(s01), f2tf32(s11)};
            uint32_t acos_[4] = {f2tf32(c00), f2tf32(c10), f2tf32(c01), f2tf32(c11)};
            mma_tf32(ct[0], asin_, breg[0][2 * c]);
            mma_tf32(ct[1], asin_, breg[1][2 * c]);
            mma_tf32(ct[0], acos_, breg[0][2 * c + 1]);
            mma_tf32(ct[1], acos_, breg[1][2 * c + 1]);
        }

#pragma unroll
        for (int tt = 0; tt < 2; tt++) {
            int gc = 8 * tt + 2 * t3;
            float v0 = fmaxf(ct[tt][0] + bias[tt][0], 0.f) + 1e-6f;
            float v1 = fmaxf(ct[tt][1] + bias[tt][1], 0.f) + 1e-6f;
            float v2 = fmaxf(ct[tt][2] + bias[tt][0], 0.f) + 1e-6f;
            float v3 = fmaxf(ct[tt][3] + bias[tt][1], 0.f) + 1e-6f;
            Lpn[(size_t)gc * MM + m0p]       = __float2half_rn(v0);
            Lpn[(size_t)(gc + 1) * MM + m0p] = __float2half_rn(v1);
            Lpn[(size_t)gc * MM + m1p]       = __float2half_rn(v2);
            Lpn[(size_t)(gc + 1) * MM + m1p] = __float2half_rn(v3);
        }
    }
}

// ===========================================================================
// Prelude dispatcher (unchanged mapping, 1312 blocks).
// ===========================================================================
__global__ void __launch_bounds__(256, 2) prelude_kernel(
    const float* __restrict__ bbox, const float* __restrict__ ref_bbox,
    const float* __restrict__ Wg_w, const float* __restrict__ Wg_b,
    const float* __restrict__ Wq_b, const float* __restrict__ Wk_b,
    const float* __restrict__ Wv_b, const float* __restrict__ u,
    float* __restrict__ Qd, __half* __restrict__ Kd, __half* __restrict__ VTd)
{
    const int bid = blockIdx.x;
    int proj = -1, posc = -1;
    if (bid < 576) {
        if ((bid & 1) == 0) proj = bid >> 1;
        else posc = bid >> 1;
    } else {
        posc = bid - 288;
    }

    if (posc >= 0) {
        pos_body(posc >> 1, posc & 1, bbox, ref_bbox, Wg_w, Wg_b);
        return;
    }

    const __half *A, *B;
    const float *cb0, *cb1 = nullptr;
    void* C;
    int i0, j0, mode;
    float alpha;
    if (proj < 32) {
        int bx = proj & 7, by = proj >> 3;
        A = g_roi_h; B = g_Wq_h; C = Qd; cb0 = Wq_b; cb1 = u;
        i0 = by * 128; j0 = bx * 128; mode = 0; alpha = 0.125f;
    } else {
        int p = proj - 32;
        int bx = p & 15, by = p >> 4;
        A = g_ref_h;
        i0 = by * 128; j0 = bx * 128; alpha = 1.f;
        if (j0 < FF) { B = g_Wk_h; C = Kd; cb0 = Wk_b; mode = 1; }
        else         { B = g_Wv_h; C = VTd; cb0 = Wv_b; mode = 2; j0 -= FF; }
    }
    proj_body(A, FF, B, FF, C, FF, FF, alpha, cb0, cb1, i0, j0, mode);
}

// ===========================================================================
// Flash attention (fp16 mma + ldmatrix fragments). block = (n-tile 64, head,
// split). 2 blocks/SM. K pitch 144B / V,P pitch 272B are ldmatrix
// conflict-free (row starts 16*i mod 128 cover distinct 16B spans).
// ===========================================================================
#define KB_U32 (128 * 36)
#define VB_U32 (64 * 68)
#define PP_U32 68
#define FLASH_SMEM_BYTES ((2 * KB_U32 + 2 * VB_U32 + 64 * PP_U32) * 4)
#define FL_TILES ((MM / SPLIT) / 128)   // 8

__global__ void __launch_bounds__(256, 2) flash_kernel()
{
    extern __shared__ uint32_t smem[];
    uint32_t* sK = smem;                           // [2][128][36] u32
    uint32_t* sV = smem + 2 * KB_U32;              // [2][64][68] u32
    uint32_t* sP = smem + 2 * KB_U32 + 2 * VB_U32; // [64][68] u32

    __shared__ float sRmax[2][64];
    __shared__ float sRsum[2][64];

    const int t = threadIdx.x;
    const int w = t >> 5, lane = t & 31;
    const int g5 = lane >> 2, t3 = lane & 3;
    const int wr = w & 3, wc = w >> 2;
    const int n0 = blockIdx.x * 64;
    const int g = blockIdx.y;
    const int sp = blockIdx.z;
    const int m_base = sp * (MM / SPLIT);

    const uint32_t kb = (uint32_t)__cvta_generic_to_shared(sK);
    const uint32_t vb = (uint32_t)__cvta_generic_to_shared(sV);
    const uint32_t pb = (uint32_t)__cvta_generic_to_shared(sP);

    // ---- Q tile (64x64 fp32, pre-scaled) -> staging -> fp16 fragments ---
    {
        float* sPf = (float*)sP;
#pragma unroll
        for (int i = 0; i < 4; i++) {
            int f = t + i * 256;
            int row = f >> 4, c4 = (f & 15) << 2;
            *(float4*)&sPf[row * 68 + c4] =
                *(const float4*)(g_Q + (size_t)(n0 + row) * FF + g * 64 + c4);
        }
    }
    __syncthreads();
    const int rl0 = 16 * wr + g5, rl1 = rl0 + 8;
    uint32_t qf[4][4];
    {
        const float* sPf = (const float*)sP;
        int r = 16 * wr + g5;
#pragma unroll
        for (int s = 0; s < 4; s++) {
            float2 x0 = *(const float2*)&sPf[r * 68 + 16 * s + 2 * t3];
            float2 x1 = *(const float2*)&sPf[(r + 8) * 68 + 16 * s + 2 * t3];
            float2 x2 = *(const float2*)&sPf[r * 68 + 16 * s + 2 * t3 + 8];
            float2 x3 = *(const float2*)&sPf[(r + 8) * 68 + 16 * s + 2 * t3 + 8];
            qf[s][0] = packh2(x0.x, x0.y);
            qf[s][1] = packh2(x1.x, x1.y);
            qf[s][2] = packh2(x2.x, x2.y);
            qf[s][3] = packh2(x3.x, x3.y);
        }
    }

    // ---- K / V^T tile loaders (cp.async, fp16) --------------------------
    auto load_kv = [&](int buf, int m0) {
#pragma unroll
        for (int i = 0; i < 4; i++) {            // K: 128 rows x 128B
            int f = t + i * 256;
            int row = f >> 3, h8 = (f & 7) * 8;
            cp16(kb + (uint32_t)((buf * KB_U32 + row * 36) * 4 + h8 * 2),
                 g_K + (size_t)(m0 + row) * FF + g * 64 + h8);
        }
#pragma unroll
        for (int i = 0; i < 4; i++) {            // VT: 64 rows x 256B
            int f = t + i * 256;
            int row = f >> 4, h8 = (f & 15) * 8;
            cp16(vb + (uint32_t)((buf * VB_U32 + row * 68) * 4 + h8 * 2),
                 g_VT + (size_t)(g * 64 + row) * MM + m0 + h8);
        }
        asm volatile("cp.async.commit_group;");
    };

    load_kv(0, m_base);
    __syncthreads();   // Q staging in sP consumed before first P write

    // ldmatrix per-lane addresses
    // K (B-frag x4 = s0h0,s0h1,s1h0,s1h1 per tn): rows 64wc+8tn+(l&7),
    // byte chunk (l>>3)*16; per tn stride 8*144; second group +64.
    const uint32_t kLane = kb
        + (uint32_t)((64 * wc + (lane & 7)) * 144 + (lane >> 3) * 16);
    // V (B-frag x4 per (td,sq)): rows 32wc+8td+(l&7), chunk sq*64+(l>>3)*16
    const uint32_t vLane = vb
        + (uint32_t)((32 * wc + (lane & 7)) * 272 + (lane >> 3) * 16);
    // P (A-frag x4 per s): rows 16wr+(l&7)+((l>>3)&1)*8, chunk 32s+(l&16?16:0)
    const uint32_t pLane = pb
        + (uint32_t)((16 * wr + (lane & 7) + ((lane >> 3) & 1) * 8) * 272
                     + ((lane & 16) ? 16 : 0));

    float rmax0 = -1e30f, rmax1 = -1e30f, rsum0 = 0.f, rsum1 = 0.f;
    float oc[4][4];
#pragma unroll
    for (int a = 0; a < 4; a++)
#pragma unroll
        for (int b = 0; b < 4; b++) oc[a][b] = 0.f;

    for (int mt = 0; mt < FL_TILES; mt++) {
        if (mt + 1 < FL_TILES) {
            load_kv((mt + 1) & 1, m_base + (mt + 1) * 128);
            asm volatile("cp.async.wait_group 1;");
        } else {
            asm volatile("cp.async.wait_group 0;");
        }
        __syncthreads();

        const uint32_t kBuf = kLane + (uint32_t)((mt & 1) * (KB_U32 * 4));
        const uint32_t vBuf = vLane + (uint32_t)((mt & 1) * (VB_U32 * 4));

        // pos weights (fp16, multiplicative)
        __half2 lp0[8], lp1[8];
        {
            size_t base0 = ((size_t)(n0 + rl0) * GG + g) * MM
                         + m_base + mt * 128 + 64 * wc + 2 * t3;
            size_t base1 = base0 + (size_t)8 * GG * MM;
#pragma unroll
            for (int tn = 0; tn < 8; tn++) {
                lp0[tn] = *(const __half2*)(g_L + base0 + 8 * tn);
                lp1[tn] = *(const __half2*)(g_L + base1 + 8 * tn);
            }
        }

        // ---- S = Q K^T (ldmatrix K fragments) ----------------------------
        float sc[8][4];
#pragma unroll
        for (int a = 0; a < 8; a++)
#pragma unroll
            for (int b = 0; b < 4; b++) sc[a][b] = 0.f;
#pragma unroll
        for (int tn = 0; tn < 8; tn++) {
            uint32_t bk[4];
            ldsm_x4(bk, kBuf + tn * 1152);
            mma_f16(sc[tn], qf[0], &bk[0]);
            mma_f16(sc[tn], qf[1], &bk[2]);
            ldsm_x4(bk, kBuf + tn * 1152 + 64);
            mma_f16(sc[tn], qf[2], &bk[0]);
            mma_f16(sc[tn], qf[3], &bk[2]);
        }

        // content-score max
        float pm0 = -1e30f, pm1 = -1e30f;
#pragma unroll
        for (int tn = 0; tn < 8; tn++) {
            pm0 = fmaxf(pm0, fmaxf(sc[tn][0], sc[tn][1]));
            pm1 = fmaxf(pm1, fmaxf(sc[tn][2], sc[tn][3]));
        }
        pm0 = fmaxf(pm0, __shfl_xor_sync(~0u, pm0, 1));
        pm0 = fmaxf(pm0, __shfl_xor_sync(~0u, pm0, 2));
        pm1 = fmaxf(pm1, __shfl_xor_sync(~0u, pm1, 1));
        pm1 = fmaxf(pm1, __shfl_xor_sync(~0u, pm1, 2));
        if (t3 == 0) { sRmax[wc][rl0] = pm0; sRmax[wc][rl1] = pm1; }
        __syncthreads();

        float nm0 = fmaxf(rmax0, fmaxf(sRmax[0][rl0], sRmax[1][rl0]));
        float nm1 = fmaxf(rmax1, fmaxf(sRmax[0][rl1], sRmax[1][rl1]));
        float fs0 = __expf(rmax0 - nm0);
        float fs1 = __expf(rmax1 - nm1);
        rmax0 = nm0; rmax1 = nm1;
#pragma unroll
        for (int td = 0; td < 4; td++) {
            oc[td][0] *= fs0; oc[td][1] *= fs0;
            oc[td][2] *= fs1; oc[td][3] *= fs1;
        }

        // ---- P = w * exp(a - max), fp16 into sP -------------------------
        float ps0 = 0.f, ps1 = 0.f;
#pragma unroll
        for (int tn = 0; tn < 8; tn++) {
            float2 w0 = __half22float2(lp0[tn]);
            float2 w1 = __half22float2(lp1[tn]);
            float p0 = w0.x * __expf(sc[tn][0] - nm0);
            float p1 = w0.y * __expf(sc[tn][1] - nm0);
            float p2 = w1.x * __expf(sc[tn][2] - nm1);
            float p3 = w1.y * __expf(sc[tn][3] - nm1);
            ps0 += p0 + p1; ps1 += p2 + p3;
            int colq = 32 * wc + 4 * tn + t3;
            sP[rl0 * PP_U32 + colq] = packh2(p0, p1);
            sP[rl1 * PP_U32 + colq] = packh2(p2, p3);
        }
        ps0 += __shfl_xor_sync(~0u, ps0, 1);
        ps0 += __shfl_xor_sync(~0u, ps0, 2);
        ps1 += __shfl_xor_sync(~0u, ps1, 1);
        ps1 += __shfl_xor_sync(~0u, ps1, 2);
        if (t3 == 0) { sRsum[wc][rl0] = ps0; sRsum[wc][rl1] = ps1; }
        __syncthreads();

        rsum0 = rsum0 * fs0 + sRsum[0][rl0] + sRsum[1][rl0];
        rsum1 = rsum1 * fs1 + sRsum[0][rl1] + sRsum[1][rl1];

        // ---- O += P V (ldmatrix P and V fragments) ----------------------
        uint32_t aP[8][4];
#pragma unroll
        for (int s = 0; s < 8; s++)
            ldsm_x4(aP[s], pLane + s * 32);
#pragma unroll
        for (int td = 0; td < 4; td++) {
#pragma unroll
            for (int sq = 0; sq < 4; sq++) {
                uint32_t bv[4];
                ldsm_x4(bv, vBuf + td * 2176 + sq * 64);   // 8 rows * 272B
                mma_f16(oc[td], aP[2 * sq], &bv[0]);
                mma_f16(oc[td], aP[2 * sq + 1], &bv[2]);
            }
        }
        __syncthreads();
    }

    // ---- partial epilogue -----------------------------------------------
    float* O0 = &g_O[sp][n0 + rl0][g * 64];
    float* O1 = O0 + (size_t)8 * FF;
#pragma unroll
    for (int td = 0; td < 4; td++) {
        int c = 32 * wc + 8 * td + 2 * t3;
        *(float2*)(O0 + c) = make_float2(oc[td][0], oc[td][1]);
        *(float2*)(O1 + c) = make_float2(oc[td][2], oc[td][3]);
    }
    if (t3 == 0 && wc == 0) {
        g_Mx[sp][n0 + rl0][g] = rmax0;     g_Sm[sp][n0 + rl0][g] = rsum0;
        g_Mx[sp][n0 + rl1][g] = rmax1;     g_Sm[sp][n0 + rl1][g] = rsum1;
    }
}

// ===========================================================================
// Combine the SPLIT partial outputs.
// ===========================================================================
__global__ void __launch_bounds__(256) combine_kernel(float* __restrict__ out)
{
    int idx = blockIdx.x * 256 + threadIdx.x;
    int n = idx / (FF / 2);
    int c = (idx - n * (FF / 2)) * 2;
    int g = c >> 6;
    float m0 = g_Mx[0][n][g], m1 = g_Mx[1][n][g];
    float Mx = fmaxf(m0, m1);
    float w0 = __expf(m0 - Mx), w1 = __expf(m1 - Mx);
    float inv = 1.f / (g_Sm[0][n][g] * w0 + g_Sm[1][n][g] * w1);
    float2 a = *(const float2*)&g_O[0][n][c];
    float2 b = *(const float2*)&g_O[1][n][c];
    *(float2*)&out[(size_t)n * FF + c] =
        make_float2((a.x * w0 + b.x * w1) * inv, (a.y * w0 + b.y * w1) * inv);
}

// ===========================================================================
extern "C" void kernel_launch(void* const* d_in, const int* in_sizes, int n_in,
                              void* d_out, int out_size)
{
    (void)in_sizes; (void)n_in; (void)out_size;
    const float* bbox     = (const float*)d_in[0];
    const float* ref_bbox = (const float*)d_in[1];
    const float* roi_feat = (const float*)d_in[2];
    const float* ref_feat = (const float*)d_in[3];
    const float* Wg_w     = (const float*)d_in[4];
    const float* Wg_b     = (const float*)d_in[5];
    const float* Wq_w     = (const float*)d_in[6];
    const float* Wq_b     = (const float*)d_in[7];
    const float* Wk_w     = (const float*)d_in[8];
    const float* Wk_b     = (const float*)d_in[9];
    const float* Wv_w     = (const float*)d_in[10];
    const float* Wv_b     = (const float*)d_in[11];
    const float* u        = (const float*)d_in[12];
    float* out = (float*)d_out;

    float* Qd; __half *Kd, *VTd;
    cudaGetSymbolAddress((void**)&Qd, g_Q);
    cudaGetSymbolAddress((void**)&Kd, g_K);
    cudaGetSymbolAddress((void**)&VTd, g_VT);

    cudaFuncSetAttribute(flash_kernel,
                         cudaFuncAttributeMaxDynamicSharedMemorySize,
                         FLASH_SMEM_BYTES);

    dim3 thr(256);

    // one-pass fp32 -> fp16 conversion of all GEMM inputs
    cvt_kernel<<<CVT_BLOCKS, thr>>>(roi_feat, ref_feat, Wq_w, Wk_w, Wv_w);
    // fused prelude: pos weights (half-m quanta) + Q proj + K|V proj
    prelude_kernel<<<1312, thr>>>(bbox, ref_bbox, Wg_w, Wg_b,
                                  Wq_b, Wk_b, Wv_b, u, Qd, Kd, VTd);
    // fused attention (fp16 mma, split-K over m) + combine
    flash_kernel<<<dim3(NN / 64, GG, SPLIT), thr, FLASH_SMEM_BYTES>>>();
    combine_kernel<<<NN * FF / 2 / 256, thr>>>(out);
}